// round 7
// baseline (speedup 1.0000x reference)
#include <cuda_runtime.h>
#include <cuda_bf16.h>
#include <cstdint>

// ---------------------------------------------------------------------------
// MultiHeadAttn: conv3x3(q/k/v) via 3-term bf16-split mma.m16n8k16 implicit
// GEMM -> split heads -> masked softmax attention -> output projection.
// B=8, C=1024 (tokens), H=W=32 (spatial=1024), heads=16, d=64.
// bf16 split: w*x ~= w_hi*x_hi + w_hi*x_lo + w_lo*x_hi  (K tripled to 27648)
// ---------------------------------------------------------------------------

#define NCH   1024
#define NB    8
#define NHEAD 16
#define KTAP3 3072            // 1024 channels * 3 split terms
#define KTOT3 27648           // 9 taps * KTAP3
#define NSTAGE 432            // 27648 / 64
#define SPITCH 72             // bf16 elems per smem row (64 + pad), 144B
#define STAGE_ELEMS ((128 + 256) * SPITCH)   // 27648 bf16 per stage

// ---------------- device scratch (no allocation allowed) -------------------
__device__ __nv_bfloat16 g_Ws_q[(size_t)1024 * KTOT3];
__device__ __nv_bfloat16 g_Ws_k[(size_t)1024 * KTOT3];
__device__ __nv_bfloat16 g_Ws_v[(size_t)1024 * KTOT3];
__device__ __nv_bfloat16 g_Xs_q[(size_t)NB * 1024 * KTAP3];
__device__ __nv_bfloat16 g_Xs_k[(size_t)NB * 1024 * KTAP3];
__device__ __nv_bfloat16 g_Xs_v[(size_t)NB * 1024 * KTAP3];
__device__ float g_Qh[NB * NCH * 1024];    // [B,16,t,64]
__device__ float g_Kh[NB * NCH * 1024];
__device__ float g_Vh[NB * NCH * 1024];
__device__ float g_attn[NB * NCH * 1024];  // [B,t,1024]

// ---------------- helpers ---------------------------------------------------
__device__ __forceinline__ uint32_t smem_u32(const void* p) {
    uint32_t a;
    asm("{ .reg .u64 t; cvta.to.shared.u64 t, %1; cvt.u32.u64 %0, t; }"
        : "=r"(a) : "l"(p));
    return a;
}
__device__ __forceinline__ void cp16(uint32_t dst, const void* src, int sz) {
    asm volatile("cp.async.ca.shared.global [%0], [%1], 16, %2;"
                 :: "r"(dst), "l"(src), "r"(sz) : "memory");
}
__device__ __forceinline__ void cp_commit() {
    asm volatile("cp.async.commit_group;" ::: "memory");
}
__device__ __forceinline__ void mma_bf16(float* d, const uint32_t* a,
                                         const uint32_t* bb) {
    asm volatile(
        "mma.sync.aligned.m16n8k16.row.col.f32.bf16.bf16.f32 "
        "{%0,%1,%2,%3}, {%4,%5,%6,%7}, {%8,%9}, {%0,%1,%2,%3};"
        : "+f"(d[0]), "+f"(d[1]), "+f"(d[2]), "+f"(d[3])
        : "r"(a[0]), "r"(a[1]), "r"(a[2]), "r"(a[3]), "r"(bb[0]), "r"(bb[1]));
}

// ---------------------------------------------------------------------------
// Weight prep: W[o,i,tap] -> Ws[o][tap*3072 + 3i + {0,1,2}] = (hi, hi, lo)
// ---------------------------------------------------------------------------
__global__ void wprep_kernel(const float* __restrict__ W,
                             __nv_bfloat16* __restrict__ Ws)
{
    int idx = blockIdx.x * 256 + threadIdx.x;      // o*9216 + i*9 + tap
    int tap = idx % 9;
    int rem = idx / 9;
    int i = rem & 1023;
    int o = rem >> 10;
    float v = W[idx];
    __nv_bfloat16 hi = __float2bfloat16(v);
    __nv_bfloat16 lo = __float2bfloat16(v - __bfloat162float(hi));
    size_t base = (size_t)o * KTOT3 + tap * KTAP3 + 3 * i;
    Ws[base + 0] = hi;
    Ws[base + 1] = hi;
    Ws[base + 2] = lo;
}

// ---------------------------------------------------------------------------
// Input prep (smem-tiled transpose):
//   x[b,i,p] -> Xs[b][p][3i + {0,1,2}] = (hi, lo, hi)
// Block: 64 i x 64 p tile, coalesced read and float4 coalesced write.
// ---------------------------------------------------------------------------
__global__ __launch_bounds__(256) void xprep_kernel(
    const float* __restrict__ x, __nv_bfloat16* __restrict__ Xs)
{
    __shared__ __nv_bfloat16 sT[64][200];          // [p][3i], 400B pitch
    const int b  = blockIdx.z;
    const int i0 = blockIdx.y * 64;
    const int p0 = blockIdx.x * 64;
    const int tid = threadIdx.x;

    #pragma unroll
    for (int it = 0; it < 16; it++) {
        int idx = tid + it * 256;                  // 4096 elems
        int r = idx >> 6, c = idx & 63;            // i = i0+r, p = p0+c
        float v = x[((size_t)b << 20) + (size_t)(i0 + r) * 1024 + p0 + c];
        __nv_bfloat16 hi = __float2bfloat16(v);
        __nv_bfloat16 lo = __float2bfloat16(v - __bfloat162float(hi));
        sT[c][3 * r + 0] = hi;
        sT[c][3 * r + 1] = lo;
        sT[c][3 * r + 2] = hi;
    }
    __syncthreads();
    #pragma unroll
    for (int it = 0; it < 6; it++) {
        int w = tid + it * 256;                    // 1536 float4
        int row = w / 24, c4 = w % 24;
        float4 val = *(const float4*)&sT[row][c4 * 8];
        *(float4*)(Xs + ((size_t)(b * 1024 + p0 + row)) * KTAP3 +
                   3 * i0 + c4 * 8) = val;
    }
}

// ---------------------------------------------------------------------------
// bf16-split tensor-core conv GEMM.
// CTA: 128 oc (M) x 256 px (N), 512 threads, warp grid 4(m)x4(n),
// warp tile 32x64 (2 mt x 8 nt of m16n8k16). K = 27648 in 432 chunks of 64,
// 3-stage cp.async ring, one __syncthreads per stage.
// SMEM rows padded to 144B -> bank = gid*4+tig, conflict-free fragments.
// Output in head layout [B,16,t=oc,d=p&63].
// ---------------------------------------------------------------------------
__global__ __launch_bounds__(512, 1) void conv_tc_kernel(
    const __nv_bfloat16* __restrict__ Ws, const __nv_bfloat16* __restrict__ Xs,
    const float* __restrict__ bias, float* __restrict__ outH)
{
    extern __shared__ __align__(16) __nv_bfloat16 sm[];
    const int b  = blockIdx.z;
    const int m0 = blockIdx.y * 128;
    const int n0 = blockIdx.x * 256;
    const int tid  = threadIdx.x;
    const int wid  = tid >> 5, lane = tid & 31;
    const int gid  = lane >> 2, tig = lane & 3;
    const int wm   = wid >> 2, wn = wid & 3;

    const __nv_bfloat16* Wb = Ws + (size_t)m0 * KTOT3;
    const __nv_bfloat16* Xb = Xs + ((size_t)b << 10) * KTAP3;

    float acc[2][8][4];
    #pragma unroll
    for (int mt = 0; mt < 2; mt++)
        #pragma unroll
        for (int nt = 0; nt < 8; nt++)
            #pragma unroll
            for (int r = 0; r < 4; r++) acc[mt][nt][r] = 0.f;

    auto load_stage = [&](int s, int st) {
        const int tap = s / 48, kc = s - tap * 48;
        const int koffA = tap * KTAP3 + kc * 64;
        const int koffB = kc * 64;
        const int dy = tap / 3 - 1, dx = tap % 3 - 1;
        __nv_bfloat16* stA = sm + st * STAGE_ELEMS;
        __nv_bfloat16* stB = stA + 128 * SPITCH;
        #pragma unroll
        for (int it = 0; it < 2; it++) {           // A: 1024 cp16
            int idx = tid * 2 + it;
            int row = idx >> 3, c = idx & 7;
            cp16(smem_u32(stA + row * SPITCH + c * 8),
                 Wb + (size_t)row * KTOT3 + koffA + c * 8, 16);
        }
        #pragma unroll
        for (int it = 0; it < 4; it++) {           // B: 2048 cp16
            int idx = tid * 4 + it;
            int row = idx >> 3, c = idx & 7;
            int p = n0 + row;
            int ys = (p >> 5) + dy, xs = (p & 31) + dx;
            bool ok = ((unsigned)ys < 32u) && ((unsigned)xs < 32u);
            int pp = ok ? (ys * 32 + xs) : 0;
            cp16(smem_u32(stB + row * SPITCH + c * 8),
                 Xb + (size_t)pp * KTAP3 + koffB + c * 8, ok ? 16 : 0);
        }
    };

    load_stage(0, 0); cp_commit();
    load_stage(1, 1); cp_commit();

    int st = 0;                                    // stage s % 3
    for (int s = 0; s < NSTAGE; s++) {
        asm volatile("cp.async.wait_group 1;" ::: "memory");
        __syncthreads();
        if (s + 2 < NSTAGE) {
            int st2 = st + 2; if (st2 >= 3) st2 -= 3;
            load_stage(s + 2, st2);
        }
        cp_commit();                               // empty groups keep count

        const __nv_bfloat16* stA = sm + st * STAGE_ELEMS;
        const __nv_bfloat16* stB = stA + 128 * SPITCH;
        #pragma unroll
        for (int kb = 0; kb < 4; kb++) {
            const int ko = kb * 16;
            uint32_t af[2][4], bfr[8][2];
            #pragma unroll
            for (int mt = 0; mt < 2; mt++) {
                int r0 = wm * 32 + mt * 16 + gid;
                const __nv_bfloat16* pa = stA + r0 * SPITCH + ko + 2 * tig;
                af[mt][0] = *(const uint32_t*)(pa);
                af[mt][1] = *(const uint32_t*)(pa + 8 * SPITCH);
                af[mt][2] = *(const uint32_t*)(pa + 8);
                af[mt][3] = *(const uint32_t*)(pa + 8 * SPITCH + 8);
            }
            #pragma unroll
            for (int nt = 0; nt < 8; nt++) {
                int n = wn * 64 + nt * 8 + gid;
                const __nv_bfloat16* pb = stB + n * SPITCH + ko + 2 * tig;
                bfr[nt][0] = *(const uint32_t*)(pb);
                bfr[nt][1] = *(const uint32_t*)(pb + 8);
            }
            #pragma unroll
            for (int mt = 0; mt < 2; mt++)
                #pragma unroll
                for (int nt = 0; nt < 8; nt++)
                    mma_bf16(acc[mt][nt], af[mt], bfr[nt]);
        }
        if (++st >= 3) st -= 3;
    }

    // epilogue -> head layout  outH[((b*16 + p>>6)*1024 + oc)*64 + (p&63)]
    #pragma unroll
    for (int mt = 0; mt < 2; mt++) {
        int r = m0 + wm * 32 + mt * 16 + gid;
        float bv0 = bias[r], bv1 = bias[r + 8];
        #pragma unroll
        for (int nt = 0; nt < 8; nt++) {
            int p = n0 + wn * 64 + nt * 8 + tig * 2;
            size_t base = ((size_t)b * 16 + (p >> 6)) * 1024;
            size_t i00 = (base + r) * 64 + (p & 63);
            size_t i10 = (base + r + 8) * 64 + (p & 63);
            outH[i00]     = acc[mt][nt][0] + bv0;
            outH[i00 + 1] = acc[mt][nt][1] + bv0;
            outH[i10]     = acc[mt][nt][2] + bv1;
            outH[i10 + 1] = acc[mt][nt][3] + bv1;
        }
    }
}

// ---------------------------------------------------------------------------
// Streaming-softmax attention (unchanged).
// ---------------------------------------------------------------------------
__global__ __launch_bounds__(256) void attn_kernel(
    const float* __restrict__ Qh, const float* __restrict__ Kh,
    const float* __restrict__ Vh, const int* __restrict__ mask,
    float* __restrict__ out)
{
    extern __shared__ float smf[];
    float* sQ = smf;
    float* sK = smf + 64 * 65;
    float* sV = smf + 2 * 64 * 65;
    float* sP = smf + 3 * 64 * 65;

    const int b = blockIdx.z, h = blockIdx.y, t0 = blockIdx.x * 64;
    const int tid = threadIdx.x, tx = tid & 15, ty = tid >> 4;

    const size_t bh = ((size_t)b * 16 + h) * 1024 * 64;
    const float* Qb = Qh + bh;
    const float* Kb = Kh + bh;
    const float* Vb = Vh + bh;

    for (int idx = tid; idx < 64 * 64; idx += 256) {
        int r = idx >> 6, c = idx & 63;
        sQ[r * 65 + c] = Qb[(size_t)(t0 + r) * 64 + c] * 0.125f;
    }

    float m_i[4], l_i[4], O[4][4];
    #pragma unroll
    for (int mm = 0; mm < 4; mm++) {
        m_i[mm] = -1e30f; l_i[mm] = 0.f;
        #pragma unroll
        for (int nn = 0; nn < 4; nn++) O[mm][nn] = 0.f;
    }

    for (int s0 = 0; s0 < 1024; s0 += 64) {
        __syncthreads();
        for (int idx = tid; idx < 64 * 64; idx += 256) {
            int r = idx >> 6, c = idx & 63;
            sK[r * 65 + c] = Kb[(size_t)(s0 + r) * 64 + c];
            sV[r * 65 + c] = Vb[(size_t)(s0 + r) * 64 + c];
        }
        __syncthreads();

        float S[4][4];
        #pragma unroll
        for (int mm = 0; mm < 4; mm++)
            #pragma unroll
            for (int nn = 0; nn < 4; nn++) S[mm][nn] = 0.f;

        #pragma unroll 8
        for (int k = 0; k < 64; k++) {
            float a[4], bb[4];
            #pragma unroll
            for (int mm = 0; mm < 4; mm++) a[mm] = sQ[(ty * 4 + mm) * 65 + k];
            #pragma unroll
            for (int nn = 0; nn < 4; nn++) bb[nn] = sK[(tx + nn * 16) * 65 + k];
            #pragma unroll
            for (int mm = 0; mm < 4; mm++)
                #pragma unroll
                for (int nn = 0; nn < 4; nn++) S[mm][nn] += a[mm] * bb[nn];
        }

        #pragma unroll
        for (int mm = 0; mm < 4; mm++) {
            const int* mrow = mask + ((size_t)b * 1024 + t0 + ty * 4 + mm) * 1024 + s0;
            #pragma unroll
            for (int nn = 0; nn < 4; nn++)
                if (mrow[tx + nn * 16] == 0) S[mm][nn] = -1e9f;
        }

        #pragma unroll
        for (int mm = 0; mm < 4; mm++) {
            float mx = fmaxf(fmaxf(S[mm][0], S[mm][1]), fmaxf(S[mm][2], S[mm][3]));
            #pragma unroll
            for (int off = 8; off >= 1; off >>= 1)
                mx = fmaxf(mx, __shfl_xor_sync(0xffffffffu, mx, off));
            float mnew = fmaxf(m_i[mm], mx);
            float corr = __expf(m_i[mm] - mnew);
            float rs = 0.f;
            #pragma unroll
            for (int nn = 0; nn < 4; nn++) {
                float p = __expf(S[mm][nn] - mnew);
                S[mm][nn] = p;
                rs += p;
            }
            #pragma unroll
            for (int off = 8; off >= 1; off >>= 1)
                rs += __shfl_xor_sync(0xffffffffu, rs, off);
            l_i[mm] = l_i[mm] * corr + rs;
            m_i[mm] = mnew;
            #pragma unroll
            for (int nn = 0; nn < 4; nn++) O[mm][nn] *= corr;
            #pragma unroll
            for (int nn = 0; nn < 4; nn++)
                sP[(ty * 4 + mm) * 65 + tx + nn * 16] = S[mm][nn];
        }
        __syncthreads();

        #pragma unroll 8
        for (int k = 0; k < 64; k++) {
            float a[4], bb[4];
            #pragma unroll
            for (int mm = 0; mm < 4; mm++) a[mm] = sP[(ty * 4 + mm) * 65 + k];
            #pragma unroll
            for (int nn = 0; nn < 4; nn++) bb[nn] = sV[k * 65 + tx + nn * 16];
            #pragma unroll
            for (int mm = 0; mm < 4; mm++)
                #pragma unroll
                for (int nn = 0; nn < 4; nn++) O[mm][nn] += a[mm] * bb[nn];
        }
    }

    #pragma unroll
    for (int mm = 0; mm < 4; mm++) {
        float inv = 1.f / l_i[mm];
        int t = t0 + ty * 4 + mm;
        #pragma unroll
        for (int nn = 0; nn < 4; nn++)
            out[((size_t)b * 1024 + t) * 1024 + h * 64 + tx + nn * 16] = O[mm][nn] * inv;
    }
}

// ---------------------------------------------------------------------------
// Output projection (unchanged).
// ---------------------------------------------------------------------------
__global__ __launch_bounds__(256) void proj_kernel(
    const float* __restrict__ A, const float* __restrict__ Wo,
    const float* __restrict__ bo, float* __restrict__ out)
{
    __shared__ float sA[64][17];
    __shared__ float sB[64][17];
    const int m0 = blockIdx.y * 64, n0 = blockIdx.x * 64;
    const int tid = threadIdx.x, tx = tid & 15, ty = tid >> 4;

    float acc[4][4];
    #pragma unroll
    for (int mm = 0; mm < 4; mm++)
        #pragma unroll
        for (int nn = 0; nn < 4; nn++) acc[mm][nn] = 0.f;

    for (int k0 = 0; k0 < 1024; k0 += 16) {
        for (int idx = tid; idx < 1024; idx += 256) {
            int r = idx >> 4, c = idx & 15;
            sA[r][c] = A[(size_t)(m0 + r) * 1024 + k0 + c];
            sB[r][c] = Wo[(size_t)(n0 + r) * 1024 + k0 + c];
        }
        __syncthreads();
        #pragma unroll
        for (int kk = 0; kk < 16; kk++) {
            float a[4], bb[4];
            #pragma unroll
            for (int mm = 0; mm < 4; mm++) a[mm] = sA[ty * 4 + mm][kk];
            #pragma unroll
            for (int nn = 0; nn < 4; nn++) bb[nn] = sB[tx + nn * 16][kk];
            #pragma unroll
            for (int mm = 0; mm < 4; mm++)
                #pragma unroll
                for (int nn = 0; nn < 4; nn++) acc[mm][nn] += a[mm] * bb[nn];
        }
        __syncthreads();
    }

    #pragma unroll
    for (int mm = 0; mm < 4; mm++)
        #pragma unroll
        for (int nn = 0; nn < 4; nn++)
            out[(size_t)(m0 + ty * 4 + mm) * 1024 + n0 + tx + nn * 16] =
                acc[mm][nn] + bo[n0 + tx + nn * 16];
}

// ---------------------------------------------------------------------------
extern "C" void kernel_launch(void* const* d_in, const int* in_sizes, int n_in,
                              void* d_out, int out_size)
{
    const float* q   = (const float*)d_in[0];
    const float* k   = (const float*)d_in[1];
    const float* v   = (const float*)d_in[2];
    const float* Wq  = (const float*)d_in[3];
    const float* bq  = (const float*)d_in[4];
    const float* Wk  = (const float*)d_in[5];
    const float* bk  = (const float*)d_in[6];
    const float* Wv  = (const float*)d_in[7];
    const float* bv  = (const float*)d_in[8];
    const float* Wo  = (const float*)d_in[9];
    const float* bo  = (const float*)d_in[10];
    const int*   msk = (const int*)d_in[11];
    float* out = (float*)d_out;

    __nv_bfloat16 *wsq, *wsk, *wsv, *xsq, *xsk, *xsv;
    float *qh, *kh, *vh, *attn;
    cudaGetSymbolAddress((void**)&wsq, g_Ws_q);
    cudaGetSymbolAddress((void**)&wsk, g_Ws_k);
    cudaGetSymbolAddress((void**)&wsv, g_Ws_v);
    cudaGetSymbolAddress((void**)&xsq, g_Xs_q);
    cudaGetSymbolAddress((void**)&xsk, g_Xs_k);
    cudaGetSymbolAddress((void**)&xsv, g_Xs_v);
    cudaGetSymbolAddress((void**)&qh,  g_Qh);
    cudaGetSymbolAddress((void**)&kh,  g_Kh);
    cudaGetSymbolAddress((void**)&vh,  g_Vh);
    cudaGetSymbolAddress((void**)&attn, g_attn);

    // 1) bf16-split prep
    wprep_kernel<<<(1024 * 1024 * 9) / 256, 256>>>(Wq, wsq);
    wprep_kernel<<<(1024 * 1024 * 9) / 256, 256>>>(Wk, wsk);
    wprep_kernel<<<(1024 * 1024 * 9) / 256, 256>>>(Wv, wsv);
    dim3 xg(16, 16, NB);
    xprep_kernel<<<xg, 256>>>(q, xsq);
    xprep_kernel<<<xg, 256>>>(k, xsk);
    xprep_kernel<<<xg, 256>>>(v, xsv);

    // 2) tensor-core convs -> head layout
    const int conv_smem = 3 * STAGE_ELEMS * (int)sizeof(__nv_bfloat16); // 165888
    cudaFuncSetAttribute(conv_tc_kernel,
                         cudaFuncAttributeMaxDynamicSharedMemorySize, conv_smem);
    dim3 cg(4, 8, NB);
    conv_tc_kernel<<<cg, 512, conv_smem>>>(wsq, xsq, bq, qh);
    conv_tc_kernel<<<cg, 512, conv_smem>>>(wsk, xsk, bk, kh);
    conv_tc_kernel<<<cg, 512, conv_smem>>>(wsv, xsv, bv, vh);

    // 3) attention
    cudaFuncSetAttribute(attn_kernel,
                         cudaFuncAttributeMaxDynamicSharedMemorySize, 66560);
    attn_kernel<<<dim3(16, NHEAD, NB), 256, 66560>>>(qh, kh, vh, msk, attn);

    // 4) projection
    proj_kernel<<<dim3(16, 128), 256>>>(attn, Wo, bo, out);
}

// round 8
// speedup vs baseline: 1.0364x; 1.0364x over previous
#include <cuda_runtime.h>
#include <cuda_bf16.h>
#include <cstdint>

// ---------------------------------------------------------------------------
// MultiHeadAttn: conv3x3(q/k/v) via 3-term bf16-split mma.m16n8k16 implicit
// GEMM (ldmatrix fragments, 4-stage cp.async ring) -> split heads -> masked
// softmax attention -> output projection.
// B=8, C=1024 (tokens), H=W=32 (spatial=1024), heads=16, d=64.
// bf16 split: w*x ~= w_hi*x_hi + w_hi*x_lo + w_lo*x_hi  (K tripled to 27648)
// ---------------------------------------------------------------------------

#define NCH   1024
#define NB    8
#define NHEAD 16
#define KTAP3 3072            // 1024 channels * 3 split terms
#define KTOT3 27648           // 9 taps * KTAP3
#define NSTAGE 432            // 27648 / 64
#define SPITCH 72             // bf16 elems per smem row (64 + pad), 144B
#define STAGE_ELEMS ((128 + 256) * SPITCH)   // 27648 bf16 per stage
#define STAGE_BYTES (STAGE_ELEMS * 2)        // 55296 B

// ---------------- device scratch (no allocation allowed) -------------------
__device__ __nv_bfloat16 g_Ws_q[(size_t)1024 * KTOT3];
__device__ __nv_bfloat16 g_Ws_k[(size_t)1024 * KTOT3];
__device__ __nv_bfloat16 g_Ws_v[(size_t)1024 * KTOT3];
__device__ __nv_bfloat16 g_Xs_q[(size_t)NB * 1024 * KTAP3];
__device__ __nv_bfloat16 g_Xs_k[(size_t)NB * 1024 * KTAP3];
__device__ __nv_bfloat16 g_Xs_v[(size_t)NB * 1024 * KTAP3];
__device__ float g_Qh[NB * NCH * 1024];    // [B,16,t,64]
__device__ float g_Kh[NB * NCH * 1024];
__device__ float g_Vh[NB * NCH * 1024];
__device__ float g_attn[NB * NCH * 1024];  // [B,t,1024]

// ---------------- helpers ---------------------------------------------------
__device__ __forceinline__ uint32_t smem_u32(const void* p) {
    uint32_t a;
    asm("{ .reg .u64 t; cvta.to.shared.u64 t, %1; cvt.u32.u64 %0, t; }"
        : "=r"(a) : "l"(p));
    return a;
}
__device__ __forceinline__ void cp16(uint32_t dst, const void* src, int sz) {
    asm volatile("cp.async.ca.shared.global [%0], [%1], 16, %2;"
                 :: "r"(dst), "l"(src), "r"(sz) : "memory");
}
__device__ __forceinline__ void cp_commit() {
    asm volatile("cp.async.commit_group;" ::: "memory");
}
__device__ __forceinline__ void ldsm_x4(uint32_t* r, uint32_t addr) {
    asm volatile("ldmatrix.sync.aligned.m8n8.x4.shared.b16 {%0,%1,%2,%3}, [%4];"
                 : "=r"(r[0]), "=r"(r[1]), "=r"(r[2]), "=r"(r[3]) : "r"(addr));
}
__device__ __forceinline__ void mma_bf16(float* d, const uint32_t* a,
                                         const uint32_t* bb) {
    asm volatile(
        "mma.sync.aligned.m16n8k16.row.col.f32.bf16.bf16.f32 "
        "{%0,%1,%2,%3}, {%4,%5,%6,%7}, {%8,%9}, {%0,%1,%2,%3};"
        : "+f"(d[0]), "+f"(d[1]), "+f"(d[2]), "+f"(d[3])
        : "r"(a[0]), "r"(a[1]), "r"(a[2]), "r"(a[3]), "r"(bb[0]), "r"(bb[1]));
}

// ---------------------------------------------------------------------------
// Weight prep: W[o,i,tap] -> Ws[o][tap*3072 + 3i + {0,1,2}] = (hi, hi, lo)
// ---------------------------------------------------------------------------
__global__ void wprep_kernel(const float* __restrict__ W,
                             __nv_bfloat16* __restrict__ Ws)
{
    int idx = blockIdx.x * 256 + threadIdx.x;      // o*9216 + i*9 + tap
    int tap = idx % 9;
    int rem = idx / 9;
    int i = rem & 1023;
    int o = rem >> 10;
    float v = W[idx];
    __nv_bfloat16 hi = __float2bfloat16(v);
    __nv_bfloat16 lo = __float2bfloat16(v - __bfloat162float(hi));
    size_t base = (size_t)o * KTOT3 + tap * KTAP3 + 3 * i;
    Ws[base + 0] = hi;
    Ws[base + 1] = hi;
    Ws[base + 2] = lo;
}

// ---------------------------------------------------------------------------
// Input prep (smem-tiled transpose):
//   x[b,i,p] -> Xs[b][p][3i + {0,1,2}] = (hi, lo, hi)
// ---------------------------------------------------------------------------
__global__ __launch_bounds__(256) void xprep_kernel(
    const float* __restrict__ x, __nv_bfloat16* __restrict__ Xs)
{
    __shared__ __nv_bfloat16 sT[64][200];          // [p][3i], 400B pitch
    const int b  = blockIdx.z;
    const int i0 = blockIdx.y * 64;
    const int p0 = blockIdx.x * 64;
    const int tid = threadIdx.x;

    #pragma unroll
    for (int it = 0; it < 16; it++) {
        int idx = tid + it * 256;                  // 4096 elems
        int r = idx >> 6, c = idx & 63;            // i = i0+r, p = p0+c
        float v = x[((size_t)b << 20) + (size_t)(i0 + r) * 1024 + p0 + c];
        __nv_bfloat16 hi = __float2bfloat16(v);
        __nv_bfloat16 lo = __float2bfloat16(v - __bfloat162float(hi));
        sT[c][3 * r + 0] = hi;
        sT[c][3 * r + 1] = lo;
        sT[c][3 * r + 2] = hi;
    }
    __syncthreads();
    #pragma unroll
    for (int it = 0; it < 6; it++) {
        int w = tid + it * 256;                    // 1536 float4
        int row = w / 24, c4 = w % 24;
        float4 val = *(const float4*)&sT[row][c4 * 8];
        *(float4*)(Xs + ((size_t)(b * 1024 + p0 + row)) * KTAP3 +
                   3 * i0 + c4 * 8) = val;
    }
}

// ---------------------------------------------------------------------------
// bf16-split tensor-core conv GEMM.
// CTA: 128 oc (M) x 256 px (N), 512 threads, warp grid 4(m)x4(n),
// warp tile 32x64 (2 mt x 8 nt of m16n8k16). K = 27648 in 432 chunks of 64,
// 4-stage cp.async ring (wait_group 2), one __syncthreads per stage.
// Fragments via ldmatrix.x4 (6 LDSM per k16-step vs 24 LDS.32).
// SMEM rows 144B -> ldmatrix rows hit banks 4n..4n+3: conflict-free.
// Output in head layout [B,16,t=oc,d=p&63].
// ---------------------------------------------------------------------------
__global__ __launch_bounds__(512, 1) void conv_tc_kernel(
    const __nv_bfloat16* __restrict__ Ws, const __nv_bfloat16* __restrict__ Xs,
    const float* __restrict__ bias, float* __restrict__ outH)
{
    extern __shared__ __align__(16) __nv_bfloat16 sm[];
    const int b  = blockIdx.z;
    const int m0 = blockIdx.y * 128;
    const int n0 = blockIdx.x * 256;
    const int tid  = threadIdx.x;
    const int wid  = tid >> 5, lane = tid & 31;
    const int gid  = lane >> 2, tig = lane & 3;
    const int wm   = wid >> 2, wn = wid & 3;

    const __nv_bfloat16* Wb = Ws + (size_t)m0 * KTOT3;
    const __nv_bfloat16* Xb = Xs + ((size_t)b << 10) * KTAP3;

    // ldmatrix per-lane byte offsets (within a stage buffer)
    // A x4: lanes 0-15 rows m=lane&15 @k, lanes 16-31 same rows @k+8
    const uint32_t laneA = (uint32_t)(((lane & 15) * SPITCH + 8 * (lane >> 4)) * 2);
    // B x4: m0: n=lane&7 @k (lanes0-7), m1: @k+8 (8-15), m2: n+8 @k (16-23),
    //       m3: n+8 @k+8 (24-31)
    const uint32_t laneB = (uint32_t)((((lane & 7) + 8 * (lane >> 4)) * SPITCH +
                                      8 * ((lane >> 3) & 1)) * 2);
    const uint32_t smBase = smem_u32(sm);

    float acc[2][8][4];
    #pragma unroll
    for (int mt = 0; mt < 2; mt++)
        #pragma unroll
        for (int nt = 0; nt < 8; nt++)
            #pragma unroll
            for (int r = 0; r < 4; r++) acc[mt][nt][r] = 0.f;

    auto load_stage = [&](int s, int st) {
        const int tap = s / 48, kc = s - tap * 48;
        const int koffA = tap * KTAP3 + kc * 64;
        const int koffB = kc * 64;
        const int dy = tap / 3 - 1, dx = tap % 3 - 1;
        __nv_bfloat16* stA = sm + st * STAGE_ELEMS;
        __nv_bfloat16* stB = stA + 128 * SPITCH;
        #pragma unroll
        for (int it = 0; it < 2; it++) {           // A: 1024 cp16
            int idx = tid * 2 + it;
            int row = idx >> 3, c = idx & 7;
            cp16(smem_u32(stA + row * SPITCH + c * 8),
                 Wb + (size_t)row * KTOT3 + koffA + c * 8, 16);
        }
        #pragma unroll
        for (int it = 0; it < 4; it++) {           // B: 2048 cp16
            int idx = tid * 4 + it;
            int row = idx >> 3, c = idx & 7;
            int p = n0 + row;
            int ys = (p >> 5) + dy, xs = (p & 31) + dx;
            bool ok = ((unsigned)ys < 32u) && ((unsigned)xs < 32u);
            int pp = ok ? (ys * 32 + xs) : 0;
            cp16(smem_u32(stB + row * SPITCH + c * 8),
                 Xb + (size_t)pp * KTAP3 + koffB + c * 8, ok ? 16 : 0);
        }
    };

    load_stage(0, 0); cp_commit();
    load_stage(1, 1); cp_commit();
    load_stage(2, 2); cp_commit();

    int st = 0;                                    // stage s % 4
    for (int s = 0; s < NSTAGE; s++) {
        asm volatile("cp.async.wait_group 2;" ::: "memory");
        __syncthreads();
        if (s + 3 < NSTAGE) load_stage(s + 3, (st + 3) & 3);
        cp_commit();                               // empty groups keep count

        const uint32_t aA = smBase + (uint32_t)(st * STAGE_BYTES) +
                            (uint32_t)(wm * 32 * SPITCH * 2) + laneA;
        const uint32_t aB = smBase + (uint32_t)(st * STAGE_BYTES) +
                            (uint32_t)(128 * SPITCH * 2) +
                            (uint32_t)(wn * 64 * SPITCH * 2) + laneB;
        #pragma unroll
        for (int kb = 0; kb < 4; kb++) {
            const uint32_t ko = kb * 32;           // 16 bf16 = 32 B
            uint32_t af[2][4];
            ldsm_x4(af[0], aA + ko);
            ldsm_x4(af[1], aA + 16 * SPITCH * 2 + ko);
            uint32_t bf4[4][4];
            #pragma unroll
            for (int p = 0; p < 4; p++)
                ldsm_x4(bf4[p], aB + (uint32_t)(p * 16 * SPITCH * 2) + ko);
            #pragma unroll
            for (int mt = 0; mt < 2; mt++)
                #pragma unroll
                for (int p = 0; p < 4; p++) {
                    mma_bf16(acc[mt][2 * p + 0], af[mt], &bf4[p][0]);
                    mma_bf16(acc[mt][2 * p + 1], af[mt], &bf4[p][2]);
                }
        }
        st = (st + 1) & 3;
    }

    // epilogue -> head layout  outH[((b*16 + p>>6)*1024 + oc)*64 + (p&63)]
    #pragma unroll
    for (int mt = 0; mt < 2; mt++) {
        int r = m0 + wm * 32 + mt * 16 + gid;
        float bv0 = bias[r], bv1 = bias[r + 8];
        #pragma unroll
        for (int nt = 0; nt < 8; nt++) {
            int p = n0 + wn * 64 + nt * 8 + tig * 2;
            size_t base = ((size_t)b * 16 + (p >> 6)) * 1024;
            size_t i00 = (base + r) * 64 + (p & 63);
            size_t i10 = (base + r + 8) * 64 + (p & 63);
            outH[i00]     = acc[mt][nt][0] + bv0;
            outH[i00 + 1] = acc[mt][nt][1] + bv0;
            outH[i10]     = acc[mt][nt][2] + bv1;
            outH[i10 + 1] = acc[mt][nt][3] + bv1;
        }
    }
}

// ---------------------------------------------------------------------------
// Streaming-softmax attention (unchanged).
// ---------------------------------------------------------------------------
__global__ __launch_bounds__(256) void attn_kernel(
    const float* __restrict__ Qh, const float* __restrict__ Kh,
    const float* __restrict__ Vh, const int* __restrict__ mask,
    float* __restrict__ out)
{
    extern __shared__ float smf[];
    float* sQ = smf;
    float* sK = smf + 64 * 65;
    float* sV = smf + 2 * 64 * 65;
    float* sP = smf + 3 * 64 * 65;

    const int b = blockIdx.z, h = blockIdx.y, t0 = blockIdx.x * 64;
    const int tid = threadIdx.x, tx = tid & 15, ty = tid >> 4;

    const size_t bh = ((size_t)b * 16 + h) * 1024 * 64;
    const float* Qb = Qh + bh;
    const float* Kb = Kh + bh;
    const float* Vb = Vh + bh;

    for (int idx = tid; idx < 64 * 64; idx += 256) {
        int r = idx >> 6, c = idx & 63;
        sQ[r * 65 + c] = Qb[(size_t)(t0 + r) * 64 + c] * 0.125f;
    }

    float m_i[4], l_i[4], O[4][4];
    #pragma unroll
    for (int mm = 0; mm < 4; mm++) {
        m_i[mm] = -1e30f; l_i[mm] = 0.f;
        #pragma unroll
        for (int nn = 0; nn < 4; nn++) O[mm][nn] = 0.f;
    }

    for (int s0 = 0; s0 < 1024; s0 += 64) {
        __syncthreads();
        for (int idx = tid; idx < 64 * 64; idx += 256) {
            int r = idx >> 6, c = idx & 63;
            sK[r * 65 + c] = Kb[(size_t)(s0 + r) * 64 + c];
            sV[r * 65 + c] = Vb[(size_t)(s0 + r) * 64 + c];
        }
        __syncthreads();

        float S[4][4];
        #pragma unroll
        for (int mm = 0; mm < 4; mm++)
            #pragma unroll
            for (int nn = 0; nn < 4; nn++) S[mm][nn] = 0.f;

        #pragma unroll 8
        for (int k = 0; k < 64; k++) {
            float a[4], bb[4];
            #pragma unroll
            for (int mm = 0; mm < 4; mm++) a[mm] = sQ[(ty * 4 + mm) * 65 + k];
            #pragma unroll
            for (int nn = 0; nn < 4; nn++) bb[nn] = sK[(tx + nn * 16) * 65 + k];
            #pragma unroll
            for (int mm = 0; mm < 4; mm++)
                #pragma unroll
                for (int nn = 0; nn < 4; nn++) S[mm][nn] += a[mm] * bb[nn];
        }

        #pragma unroll
        for (int mm = 0; mm < 4; mm++) {
            const int* mrow = mask + ((size_t)b * 1024 + t0 + ty * 4 + mm) * 1024 + s0;
            #pragma unroll
            for (int nn = 0; nn < 4; nn++)
                if (mrow[tx + nn * 16] == 0) S[mm][nn] = -1e9f;
        }

        #pragma unroll
        for (int mm = 0; mm < 4; mm++) {
            float mx = fmaxf(fmaxf(S[mm][0], S[mm][1]), fmaxf(S[mm][2], S[mm][3]));
            #pragma unroll
            for (int off = 8; off >= 1; off >>= 1)
                mx = fmaxf(mx, __shfl_xor_sync(0xffffffffu, mx, off));
            float mnew = fmaxf(m_i[mm], mx);
            float corr = __expf(m_i[mm] - mnew);
            float rs = 0.f;
            #pragma unroll
            for (int nn = 0; nn < 4; nn++) {
                float p = __expf(S[mm][nn] - mnew);
                S[mm][nn] = p;
                rs += p;
            }
            #pragma unroll
            for (int off = 8; off >= 1; off >>= 1)
                rs += __shfl_xor_sync(0xffffffffu, rs, off);
            l_i[mm] = l_i[mm] * corr + rs;
            m_i[mm] = mnew;
            #pragma unroll
            for (int nn = 0; nn < 4; nn++) O[mm][nn] *= corr;
            #pragma unroll
            for (int nn = 0; nn < 4; nn++)
                sP[(ty * 4 + mm) * 65 + tx + nn * 16] = S[mm][nn];
        }
        __syncthreads();

        #pragma unroll 8
        for (int k = 0; k < 64; k++) {
            float a[4], bb[4];
            #pragma unroll
            for (int mm = 0; mm < 4; mm++) a[mm] = sP[(ty * 4 + mm) * 65 + k];
            #pragma unroll
            for (int nn = 0; nn < 4; nn++) bb[nn] = sV[k * 65 + tx + nn * 16];
            #pragma unroll
            for (int mm = 0; mm < 4; mm++)
                #pragma unroll
                for (int nn = 0; nn < 4; nn++) O[mm][nn] += a[mm] * bb[nn];
        }
    }

    #pragma unroll
    for (int mm = 0; mm < 4; mm++) {
        float inv = 1.f / l_i[mm];
        int t = t0 + ty * 4 + mm;
        #pragma unroll
        for (int nn = 0; nn < 4; nn++)
            out[((size_t)b * 1024 + t) * 1024 + h * 64 + tx + nn * 16] = O[mm][nn] * inv;
    }
}

// ---------------------------------------------------------------------------
// Output projection (unchanged).
// ---------------------------------------------------------------------------
__global__ __launch_bounds__(256) void proj_kernel(
    const float* __restrict__ A, const float* __restrict__ Wo,
    const float* __restrict__ bo, float* __restrict__ out)
{
    __shared__ float sA[64][17];
    __shared__ float sB[64][17];
    const int m0 = blockIdx.y * 64, n0 = blockIdx.x * 64;
    const int tid = threadIdx.x, tx = tid & 15, ty = tid >> 4;

    float acc[4][4];
    #pragma unroll
    for (int mm = 0; mm < 4; mm++)
        #pragma unroll
        for (int nn = 0; nn < 4; nn++) acc[mm][nn] = 0.f;

    for (int k0 = 0; k0 < 1024; k0 += 16) {
        for (int idx = tid; idx < 1024; idx += 256) {
            int r = idx >> 4, c = idx & 15;
            sA[r][c] = A[(size_t)(m0 + r) * 1024 + k0 + c];
            sB[r][c] = Wo[(size_t)(n0 + r) * 1024 + k0 + c];
        }
        __syncthreads();
        #pragma unroll
        for (int kk = 0; kk < 16; kk++) {
            float a[4], bb[4];
            #pragma unroll
            for (int mm = 0; mm < 4; mm++) a[mm] = sA[ty * 4 + mm][kk];
            #pragma unroll
            for (int nn = 0; nn < 4; nn++) bb[nn] = sB[tx + nn * 16][kk];
            #pragma unroll
            for (int mm = 0; mm < 4; mm++)
                #pragma unroll
                for (int nn = 0; nn < 4; nn++) acc[mm][nn] += a[mm] * bb[nn];
        }
        __syncthreads();
    }

    #pragma unroll
    for (int mm = 0; mm < 4; mm++)
        #pragma unroll
        for (int nn = 0; nn < 4; nn++)
            out[(size_t)(m0 + ty * 4 + mm) * 1024 + n0 + tx + nn * 16] =
                acc[mm][nn] + bo[n0 + tx + nn * 16];
}

// ---------------------------------------------------------------------------
extern "C" void kernel_launch(void* const* d_in, const int* in_sizes, int n_in,
                              void* d_out, int out_size)
{
    const float* q   = (const float*)d_in[0];
    const float* k   = (const float*)d_in[1];
    const float* v   = (const float*)d_in[2];
    const float* Wq  = (const float*)d_in[3];
    const float* bq  = (const float*)d_in[4];
    const float* Wk  = (const float*)d_in[5];
    const float* bk  = (const float*)d_in[6];
    const float* Wv  = (const float*)d_in[7];
    const float* bv  = (const float*)d_in[8];
    const float* Wo  = (const float*)d_in[9];
    const float* bo  = (const float*)d_in[10];
    const int*   msk = (const int*)d_in[11];
    float* out = (float*)d_out;

    __nv_bfloat16 *wsq, *wsk, *wsv, *xsq, *xsk, *xsv;
    float *qh, *kh, *vh, *attn;
    cudaGetSymbolAddress((void**)&wsq, g_Ws_q);
    cudaGetSymbolAddress((void**)&wsk, g_Ws_k);
    cudaGetSymbolAddress((void**)&wsv, g_Ws_v);
    cudaGetSymbolAddress((void**)&xsq, g_Xs_q);
    cudaGetSymbolAddress((void**)&xsk, g_Xs_k);
    cudaGetSymbolAddress((void**)&xsv, g_Xs_v);
    cudaGetSymbolAddress((void**)&qh,  g_Qh);
    cudaGetSymbolAddress((void**)&kh,  g_Kh);
    cudaGetSymbolAddress((void**)&vh,  g_Vh);
    cudaGetSymbolAddress((void**)&attn, g_attn);

    // 1) bf16-split prep
    wprep_kernel<<<(1024 * 1024 * 9) / 256, 256>>>(Wq, wsq);
    wprep_kernel<<<(1024 * 1024 * 9) / 256, 256>>>(Wk, wsk);
    wprep_kernel<<<(1024 * 1024 * 9) / 256, 256>>>(Wv, wsv);
    dim3 xg(16, 16, NB);
    xprep_kernel<<<xg, 256>>>(q, xsq);
    xprep_kernel<<<xg, 256>>>(k, xsk);
    xprep_kernel<<<xg, 256>>>(v, xsv);

    // 2) tensor-core convs -> head layout (4-stage ring: 221184 B smem)
    const int conv_smem = 4 * STAGE_BYTES;
    cudaFuncSetAttribute(conv_tc_kernel,
                         cudaFuncAttributeMaxDynamicSharedMemorySize, conv_smem);
    dim3 cg(4, 8, NB);
    conv_tc_kernel<<<cg, 512, conv_smem>>>(wsq, xsq, bq, qh);
    conv_tc_kernel<<<cg, 512, conv_smem>>>(wsk, xsk, bk, kh);
    conv_tc_kernel<<<cg, 512, conv_smem>>>(wsv, xsv, bv, vh);

    // 3) attention
    cudaFuncSetAttribute(attn_kernel,
                         cudaFuncAttributeMaxDynamicSharedMemorySize, 66560);
    attn_kernel<<<dim3(16, NHEAD, NB), 256, 66560>>>(qh, kh, vh, msk, attn);

    // 4) projection
    proj_kernel<<<dim3(16, 128), 256>>>(attn, Wo, bo, out);
}

// round 9
// speedup vs baseline: 1.1765x; 1.1352x over previous
#include <cuda_runtime.h>
#include <cuda_bf16.h>
#include <cstdint>

// ---------------------------------------------------------------------------
// MultiHeadAttn: conv3x3(q/k/v) via 3-term bf16-split mma.m16n8k16 implicit
// GEMM (64x64 warp tiles, ldmatrix, 4-stage cp.async ring) -> split heads ->
// masked softmax attention -> output projection.
// B=8, C=1024 (tokens), H=W=32 (spatial=1024), heads=16, d=64.
// bf16 split: w*x ~= w_hi*x_hi + w_hi*x_lo + w_lo*x_hi  (K tripled to 27648)
// ---------------------------------------------------------------------------

#define NCH   1024
#define NB    8
#define NHEAD 16
#define KTAP3 3072            // 1024 channels * 3 split terms
#define KTOT3 27648           // 9 taps * KTAP3
#define NSTAGE 432            // 27648 / 64
#define SPITCH 72             // bf16 elems per smem row (64 + pad), 144B
#define STAGE_ELEMS ((128 + 256) * SPITCH)   // 27648 bf16 per stage
#define STAGE_BYTES (STAGE_ELEMS * 2)        // 55296 B

// ---------------- device scratch (no allocation allowed) -------------------
__device__ __nv_bfloat16 g_Ws_q[(size_t)1024 * KTOT3];
__device__ __nv_bfloat16 g_Ws_k[(size_t)1024 * KTOT3];
__device__ __nv_bfloat16 g_Ws_v[(size_t)1024 * KTOT3];
__device__ __nv_bfloat16 g_Xs_q[(size_t)NB * 1024 * KTAP3];
__device__ __nv_bfloat16 g_Xs_k[(size_t)NB * 1024 * KTAP3];
__device__ __nv_bfloat16 g_Xs_v[(size_t)NB * 1024 * KTAP3];
__device__ float g_Qh[NB * NCH * 1024];    // [B,16,t,64]
__device__ float g_Kh[NB * NCH * 1024];
__device__ float g_Vh[NB * NCH * 1024];
__device__ float g_attn[NB * NCH * 1024];  // [B,t,1024]

// ---------------- helpers ---------------------------------------------------
__device__ __forceinline__ uint32_t smem_u32(const void* p) {
    uint32_t a;
    asm("{ .reg .u64 t; cvta.to.shared.u64 t, %1; cvt.u32.u64 %0, t; }"
        : "=r"(a) : "l"(p));
    return a;
}
__device__ __forceinline__ void cp16(uint32_t dst, const void* src, int sz) {
    asm volatile("cp.async.ca.shared.global [%0], [%1], 16, %2;"
                 :: "r"(dst), "l"(src), "r"(sz) : "memory");
}
__device__ __forceinline__ void cp_commit() {
    asm volatile("cp.async.commit_group;" ::: "memory");
}
__device__ __forceinline__ void ldsm_x4(uint32_t* r, uint32_t addr) {
    asm volatile("ldmatrix.sync.aligned.m8n8.x4.shared.b16 {%0,%1,%2,%3}, [%4];"
                 : "=r"(r[0]), "=r"(r[1]), "=r"(r[2]), "=r"(r[3]) : "r"(addr));
}
__device__ __forceinline__ void mma_bf16(float* d, const uint32_t* a,
                                         const uint32_t* bb) {
    asm volatile(
        "mma.sync.aligned.m16n8k16.row.col.f32.bf16.bf16.f32 "
        "{%0,%1,%2,%3}, {%4,%5,%6,%7}, {%8,%9}, {%0,%1,%2,%3};"
        : "+f"(d[0]), "+f"(d[1]), "+f"(d[2]), "+f"(d[3])
        : "r"(a[0]), "r"(a[1]), "r"(a[2]), "r"(a[3]), "r"(bb[0]), "r"(bb[1]));
}

// ---------------------------------------------------------------------------
// Weight prep: W[o,i,tap] -> Ws[o][tap*3072 + 3i + {0,1,2}] = (hi, hi, lo)
// ---------------------------------------------------------------------------
__global__ void wprep_kernel(const float* __restrict__ W,
                             __nv_bfloat16* __restrict__ Ws)
{
    int idx = blockIdx.x * 256 + threadIdx.x;      // o*9216 + i*9 + tap
    int tap = idx % 9;
    int rem = idx / 9;
    int i = rem & 1023;
    int o = rem >> 10;
    float v = W[idx];
    __nv_bfloat16 hi = __float2bfloat16(v);
    __nv_bfloat16 lo = __float2bfloat16(v - __bfloat162float(hi));
    size_t base = (size_t)o * KTOT3 + tap * KTAP3 + 3 * i;
    Ws[base + 0] = hi;
    Ws[base + 1] = hi;
    Ws[base + 2] = lo;
}

// ---------------------------------------------------------------------------
// Input prep (smem-tiled transpose):
//   x[b,i,p] -> Xs[b][p][3i + {0,1,2}] = (hi, lo, hi)
// ---------------------------------------------------------------------------
__global__ __launch_bounds__(256) void xprep_kernel(
    const float* __restrict__ x, __nv_bfloat16* __restrict__ Xs)
{
    __shared__ __nv_bfloat16 sT[64][200];          // [p][3i], 400B pitch
    const int b  = blockIdx.z;
    const int i0 = blockIdx.y * 64;
    const int p0 = blockIdx.x * 64;
    const int tid = threadIdx.x;

    #pragma unroll
    for (int it = 0; it < 16; it++) {
        int idx = tid + it * 256;                  // 4096 elems
        int r = idx >> 6, c = idx & 63;            // i = i0+r, p = p0+c
        float v = x[((size_t)b << 20) + (size_t)(i0 + r) * 1024 + p0 + c];
        __nv_bfloat16 hi = __float2bfloat16(v);
        __nv_bfloat16 lo = __float2bfloat16(v - __bfloat162float(hi));
        sT[c][3 * r + 0] = hi;
        sT[c][3 * r + 1] = lo;
        sT[c][3 * r + 2] = hi;
    }
    __syncthreads();
    #pragma unroll
    for (int it = 0; it < 6; it++) {
        int w = tid + it * 256;                    // 1536 float4
        int row = w / 24, c4 = w % 24;
        float4 val = *(const float4*)&sT[row][c4 * 8];
        *(float4*)(Xs + ((size_t)(b * 1024 + p0 + row)) * KTAP3 +
                   3 * i0 + c4 * 8) = val;
    }
}

// ---------------------------------------------------------------------------
// bf16-split tensor-core conv GEMM.
// CTA: 128 oc (M) x 256 px (N), 256 threads, warp grid 2(m)x4(n),
// warp tile 64x64 (4 mt x 8 nt of m16n8k16) -> smem read traffic factor
// (1/64+1/64) vs (1/32+1/64): 1.5x less than R8; smem crossbar was the binder.
// K = 27648 in 432 chunks of 64, 4-stage cp.async ring (wait_group 2).
// Fragments via ldmatrix.x4; 144B row pitch -> conflict-free.
// Output in head layout [B,16,t=oc,d=p&63].
// ---------------------------------------------------------------------------
__global__ __launch_bounds__(256, 1) void conv_tc_kernel(
    const __nv_bfloat16* __restrict__ Ws, const __nv_bfloat16* __restrict__ Xs,
    const float* __restrict__ bias, float* __restrict__ outH)
{
    extern __shared__ __align__(16) __nv_bfloat16 sm[];
    const int b  = blockIdx.z;
    const int m0 = blockIdx.y * 128;
    const int n0 = blockIdx.x * 256;
    const int tid  = threadIdx.x;
    const int wid  = tid >> 5, lane = tid & 31;
    const int gid  = lane >> 2, tig = lane & 3;
    const int wm   = wid >> 2, wn = wid & 3;       // 2 x 4 warp grid

    const __nv_bfloat16* Wb = Ws + (size_t)m0 * KTOT3;
    const __nv_bfloat16* Xb = Xs + ((size_t)b << 10) * KTAP3;

    // ldmatrix per-lane byte offsets (within a stage buffer)
    const uint32_t laneA = (uint32_t)(((lane & 15) * SPITCH + 8 * (lane >> 4)) * 2);
    const uint32_t laneB = (uint32_t)((((lane & 7) + 8 * (lane >> 4)) * SPITCH +
                                      8 * ((lane >> 3) & 1)) * 2);
    const uint32_t smBase = smem_u32(sm);

    float acc[4][8][4];
    #pragma unroll
    for (int mt = 0; mt < 4; mt++)
        #pragma unroll
        for (int nt = 0; nt < 8; nt++)
            #pragma unroll
            for (int r = 0; r < 4; r++) acc[mt][nt][r] = 0.f;

    auto load_stage = [&](int s, int st) {
        const int tap = s / 48, kc = s - tap * 48;
        const int koffA = tap * KTAP3 + kc * 64;
        const int koffB = kc * 64;
        const int dy = tap / 3 - 1, dx = tap % 3 - 1;
        __nv_bfloat16* stA = sm + st * STAGE_ELEMS;
        __nv_bfloat16* stB = stA + 128 * SPITCH;
        #pragma unroll
        for (int it = 0; it < 4; it++) {           // A: 1024 cp16, coalesced
            int idx = tid + it * 256;
            int row = idx >> 3, c = idx & 7;
            cp16(smem_u32(stA + row * SPITCH + c * 8),
                 Wb + (size_t)row * KTOT3 + koffA + c * 8, 16);
        }
        #pragma unroll
        for (int it = 0; it < 8; it++) {           // B: 2048 cp16, coalesced
            int idx = tid + it * 256;
            int row = idx >> 3, c = idx & 7;
            int p = n0 + row;
            int ys = (p >> 5) + dy, xs = (p & 31) + dx;
            bool ok = ((unsigned)ys < 32u) && ((unsigned)xs < 32u);
            int pp = ok ? (ys * 32 + xs) : 0;
            cp16(smem_u32(stB + row * SPITCH + c * 8),
                 Xb + (size_t)pp * KTAP3 + koffB + c * 8, ok ? 16 : 0);
        }
    };

    load_stage(0, 0); cp_commit();
    load_stage(1, 1); cp_commit();
    load_stage(2, 2); cp_commit();

    int st = 0;                                    // stage s % 4
    for (int s = 0; s < NSTAGE; s++) {
        asm volatile("cp.async.wait_group 2;" ::: "memory");
        __syncthreads();
        if (s + 3 < NSTAGE) load_stage(s + 3, (st + 3) & 3);
        cp_commit();                               // empty groups keep count

        const uint32_t aA = smBase + (uint32_t)(st * STAGE_BYTES) +
                            (uint32_t)(wm * 64 * SPITCH * 2) + laneA;
        const uint32_t aB = smBase + (uint32_t)(st * STAGE_BYTES) +
                            (uint32_t)(128 * SPITCH * 2) +
                            (uint32_t)(wn * 64 * SPITCH * 2) + laneB;
        #pragma unroll
        for (int kb = 0; kb < 4; kb++) {
            const uint32_t ko = kb * 32;           // 16 bf16 = 32 B
            uint32_t af[4][4];
            #pragma unroll
            for (int mt = 0; mt < 4; mt++)
                ldsm_x4(af[mt], aA + (uint32_t)(mt * 16 * SPITCH * 2) + ko);
            uint32_t bf4[4][4];
            #pragma unroll
            for (int p = 0; p < 4; p++)
                ldsm_x4(bf4[p], aB + (uint32_t)(p * 16 * SPITCH * 2) + ko);
            #pragma unroll
            for (int mt = 0; mt < 4; mt++)
                #pragma unroll
                for (int p = 0; p < 4; p++) {
                    mma_bf16(acc[mt][2 * p + 0], af[mt], &bf4[p][0]);
                    mma_bf16(acc[mt][2 * p + 1], af[mt], &bf4[p][2]);
                }
        }
        st = (st + 1) & 3;
    }

    // epilogue -> head layout  outH[((b*16 + p>>6)*1024 + oc)*64 + (p&63)]
    #pragma unroll
    for (int mt = 0; mt < 4; mt++) {
        int r = m0 + wm * 64 + mt * 16 + gid;
        float bv0 = bias[r], bv1 = bias[r + 8];
        #pragma unroll
        for (int nt = 0; nt < 8; nt++) {
            int p = n0 + wn * 64 + nt * 8 + tig * 2;
            size_t base = ((size_t)b * 16 + (p >> 6)) * 1024;
            size_t i00 = (base + r) * 64 + (p & 63);
            size_t i10 = (base + r + 8) * 64 + (p & 63);
            outH[i00]     = acc[mt][nt][0] + bv0;
            outH[i00 + 1] = acc[mt][nt][1] + bv0;
            outH[i10]     = acc[mt][nt][2] + bv1;
            outH[i10 + 1] = acc[mt][nt][3] + bv1;
        }
    }
}

// ---------------------------------------------------------------------------
// Streaming-softmax attention (unchanged).
// ---------------------------------------------------------------------------
__global__ __launch_bounds__(256) void attn_kernel(
    const float* __restrict__ Qh, const float* __restrict__ Kh,
    const float* __restrict__ Vh, const int* __restrict__ mask,
    float* __restrict__ out)
{
    extern __shared__ float smf[];
    float* sQ = smf;
    float* sK = smf + 64 * 65;
    float* sV = smf + 2 * 64 * 65;
    float* sP = smf + 3 * 64 * 65;

    const int b = blockIdx.z, h = blockIdx.y, t0 = blockIdx.x * 64;
    const int tid = threadIdx.x, tx = tid & 15, ty = tid >> 4;

    const size_t bh = ((size_t)b * 16 + h) * 1024 * 64;
    const float* Qb = Qh + bh;
    const float* Kb = Kh + bh;
    const float* Vb = Vh + bh;

    for (int idx = tid; idx < 64 * 64; idx += 256) {
        int r = idx >> 6, c = idx & 63;
        sQ[r * 65 + c] = Qb[(size_t)(t0 + r) * 64 + c] * 0.125f;
    }

    float m_i[4], l_i[4], O[4][4];
    #pragma unroll
    for (int mm = 0; mm < 4; mm++) {
        m_i[mm] = -1e30f; l_i[mm] = 0.f;
        #pragma unroll
        for (int nn = 0; nn < 4; nn++) O[mm][nn] = 0.f;
    }

    for (int s0 = 0; s0 < 1024; s0 += 64) {
        __syncthreads();
        for (int idx = tid; idx < 64 * 64; idx += 256) {
            int r = idx >> 6, c = idx & 63;
            sK[r * 65 + c] = Kb[(size_t)(s0 + r) * 64 + c];
            sV[r * 65 + c] = Vb[(size_t)(s0 + r) * 64 + c];
        }
        __syncthreads();

        float S[4][4];
        #pragma unroll
        for (int mm = 0; mm < 4; mm++)
            #pragma unroll
            for (int nn = 0; nn < 4; nn++) S[mm][nn] = 0.f;

        #pragma unroll 8
        for (int k = 0; k < 64; k++) {
            float a[4], bb[4];
            #pragma unroll
            for (int mm = 0; mm < 4; mm++) a[mm] = sQ[(ty * 4 + mm) * 65 + k];
            #pragma unroll
            for (int nn = 0; nn < 4; nn++) bb[nn] = sK[(tx + nn * 16) * 65 + k];
            #pragma unroll
            for (int mm = 0; mm < 4; mm++)
                #pragma unroll
                for (int nn = 0; nn < 4; nn++) S[mm][nn] += a[mm] * bb[nn];
        }

        #pragma unroll
        for (int mm = 0; mm < 4; mm++) {
            const int* mrow = mask + ((size_t)b * 1024 + t0 + ty * 4 + mm) * 1024 + s0;
            #pragma unroll
            for (int nn = 0; nn < 4; nn++)
                if (mrow[tx + nn * 16] == 0) S[mm][nn] = -1e9f;
        }

        #pragma unroll
        for (int mm = 0; mm < 4; mm++) {
            float mx = fmaxf(fmaxf(S[mm][0], S[mm][1]), fmaxf(S[mm][2], S[mm][3]));
            #pragma unroll
            for (int off = 8; off >= 1; off >>= 1)
                mx = fmaxf(mx, __shfl_xor_sync(0xffffffffu, mx, off));
            float mnew = fmaxf(m_i[mm], mx);
            float corr = __expf(m_i[mm] - mnew);
            float rs = 0.f;
            #pragma unroll
            for (int nn = 0; nn < 4; nn++) {
                float p = __expf(S[mm][nn] - mnew);
                S[mm][nn] = p;
                rs += p;
            }
            #pragma unroll
            for (int off = 8; off >= 1; off >>= 1)
                rs += __shfl_xor_sync(0xffffffffu, rs, off);
            l_i[mm] = l_i[mm] * corr + rs;
            m_i[mm] = mnew;
            #pragma unroll
            for (int nn = 0; nn < 4; nn++) O[mm][nn] *= corr;
            #pragma unroll
            for (int nn = 0; nn < 4; nn++)
                sP[(ty * 4 + mm) * 65 + tx + nn * 16] = S[mm][nn];
        }
        __syncthreads();

        #pragma unroll 8
        for (int k = 0; k < 64; k++) {
            float a[4], bb[4];
            #pragma unroll
            for (int mm = 0; mm < 4; mm++) a[mm] = sP[(ty * 4 + mm) * 65 + k];
            #pragma unroll
            for (int nn = 0; nn < 4; nn++) bb[nn] = sV[k * 65 + tx + nn * 16];
            #pragma unroll
            for (int mm = 0; mm < 4; mm++)
                #pragma unroll
                for (int nn = 0; nn < 4; nn++) O[mm][nn] += a[mm] * bb[nn];
        }
    }

    #pragma unroll
    for (int mm = 0; mm < 4; mm++) {
        float inv = 1.f / l_i[mm];
        int t = t0 + ty * 4 + mm;
        #pragma unroll
        for (int nn = 0; nn < 4; nn++)
            out[((size_t)b * 1024 + t) * 1024 + h * 64 + tx + nn * 16] = O[mm][nn] * inv;
    }
}

// ---------------------------------------------------------------------------
// Output projection (unchanged).
// ---------------------------------------------------------------------------
__global__ __launch_bounds__(256) void proj_kernel(
    const float* __restrict__ A, const float* __restrict__ Wo,
    const float* __restrict__ bo, float* __restrict__ out)
{
    __shared__ float sA[64][17];
    __shared__ float sB[64][17];
    const int m0 = blockIdx.y * 64, n0 = blockIdx.x * 64;
    const int tid = threadIdx.x, tx = tid & 15, ty = tid >> 4;

    float acc[4][4];
    #pragma unroll
    for (int mm = 0; mm < 4; mm++)
        #pragma unroll
        for (int nn = 0; nn < 4; nn++) acc[mm][nn] = 0.f;

    for (int k0 = 0; k0 < 1024; k0 += 16) {
        for (int idx = tid; idx < 1024; idx += 256) {
            int r = idx >> 4, c = idx & 15;
            sA[r][c] = A[(size_t)(m0 + r) * 1024 + k0 + c];
            sB[r][c] = Wo[(size_t)(n0 + r) * 1024 + k0 + c];
        }
        __syncthreads();
        #pragma unroll
        for (int kk = 0; kk < 16; kk++) {
            float a[4], bb[4];
            #pragma unroll
            for (int mm = 0; mm < 4; mm++) a[mm] = sA[ty * 4 + mm][kk];
            #pragma unroll
            for (int nn = 0; nn < 4; nn++) bb[nn] = sB[tx + nn * 16][kk];
            #pragma unroll
            for (int mm = 0; mm < 4; mm++)
                #pragma unroll
                for (int nn = 0; nn < 4; nn++) acc[mm][nn] += a[mm] * bb[nn];
        }
        __syncthreads();
    }

    #pragma unroll
    for (int mm = 0; mm < 4; mm++)
        #pragma unroll
        for (int nn = 0; nn < 4; nn++)
            out[(size_t)(m0 + ty * 4 + mm) * 1024 + n0 + tx + nn * 16] =
                acc[mm][nn] + bo[n0 + tx + nn * 16];
}

// ---------------------------------------------------------------------------
extern "C" void kernel_launch(void* const* d_in, const int* in_sizes, int n_in,
                              void* d_out, int out_size)
{
    const float* q   = (const float*)d_in[0];
    const float* k   = (const float*)d_in[1];
    const float* v   = (const float*)d_in[2];
    const float* Wq  = (const float*)d_in[3];
    const float* bq  = (const float*)d_in[4];
    const float* Wk  = (const float*)d_in[5];
    const float* bk  = (const float*)d_in[6];
    const float* Wv  = (const float*)d_in[7];
    const float* bv  = (const float*)d_in[8];
    const float* Wo  = (const float*)d_in[9];
    const float* bo  = (const float*)d_in[10];
    const int*   msk = (const int*)d_in[11];
    float* out = (float*)d_out;

    __nv_bfloat16 *wsq, *wsk, *wsv, *xsq, *xsk, *xsv;
    float *qh, *kh, *vh, *attn;
    cudaGetSymbolAddress((void**)&wsq, g_Ws_q);
    cudaGetSymbolAddress((void**)&wsk, g_Ws_k);
    cudaGetSymbolAddress((void**)&wsv, g_Ws_v);
    cudaGetSymbolAddress((void**)&xsq, g_Xs_q);
    cudaGetSymbolAddress((void**)&xsk, g_Xs_k);
    cudaGetSymbolAddress((void**)&xsv, g_Xs_v);
    cudaGetSymbolAddress((void**)&qh,  g_Qh);
    cudaGetSymbolAddress((void**)&kh,  g_Kh);
    cudaGetSymbolAddress((void**)&vh,  g_Vh);
    cudaGetSymbolAddress((void**)&attn, g_attn);

    // 1) bf16-split prep
    wprep_kernel<<<(1024 * 1024 * 9) / 256, 256>>>(Wq, wsq);
    wprep_kernel<<<(1024 * 1024 * 9) / 256, 256>>>(Wk, wsk);
    wprep_kernel<<<(1024 * 1024 * 9) / 256, 256>>>(Wv, wsv);
    dim3 xg(16, 16, NB);
    xprep_kernel<<<xg, 256>>>(q, xsq);
    xprep_kernel<<<xg, 256>>>(k, xsk);
    xprep_kernel<<<xg, 256>>>(v, xsv);

    // 2) tensor-core convs -> head layout (4-stage ring: 221184 B smem)
    const int conv_smem = 4 * STAGE_BYTES;
    cudaFuncSetAttribute(conv_tc_kernel,
                         cudaFuncAttributeMaxDynamicSharedMemorySize, conv_smem);
    dim3 cg(4, 8, NB);
    conv_tc_kernel<<<cg, 256, conv_smem>>>(wsq, xsq, bq, qh);
    conv_tc_kernel<<<cg, 256, conv_smem>>>(wsk, xsk, bk, kh);
    conv_tc_kernel<<<cg, 256, conv_smem>>>(wsv, xsv, bv, vh);

    // 3) attention
    cudaFuncSetAttribute(attn_kernel,
                         cudaFuncAttributeMaxDynamicSharedMemorySize, 66560);
    attn_kernel<<<dim3(16, NHEAD, NB), 256, 66560>>>(qh, kh, vh, msk, attn);

    // 4) projection
    proj_kernel<<<dim3(16, 128), 256>>>(attn, Wo, bo, out);
}

// round 11
// speedup vs baseline: 1.8028x; 1.5323x over previous
#include <cuda_runtime.h>
#include <cuda_fp16.h>
#include <cstdint>

// ---------------------------------------------------------------------------
// MultiHeadAttn: conv3x3(q/k/v) via 2-term fp16-split mma.m16n8k16 implicit
// GEMM (shared-B dual-plane A, 64x64 warp tiles, ldmatrix, 3-stage cp.async
// ring) -> split heads -> masked softmax attention (FMA-pipe exp) -> proj.
// B=8, C=1024 (tokens), H=W=32 (spatial=1024), heads=16, d=64.
// Split: w*x = (w_hi + w_lo)*x, w_hi/w_lo fp16 (pre-scaled by 512 to avoid
// fp16 subnormals in w_lo), x fp16. One B tile serves both A planes.
// ---------------------------------------------------------------------------

#define NCH   1024
#define NB    8
#define NHEAD 16
#define KC    9216            // 9 taps * 1024 channels (per A plane)
#define NSTAGE 144            // 9216 / 64
#define SPITCH 72             // fp16 elems per smem row (64 + pad), 144B
#define STAGE_ELEMS ((128 + 128 + 256) * SPITCH)   // A_hi + A_lo + B
#define STAGE_BYTES (STAGE_ELEMS * 2)              // 73728 B
#define OFF_ALO (128 * SPITCH * 2)
#define OFF_B   (256 * SPITCH * 2)
#define WSCALE   512.0f
#define INV_WSCALE 0.001953125f

// ---------------- device scratch (no allocation allowed) -------------------
__device__ __half g_Wh_q[(size_t)1024 * KC];
__device__ __half g_Wl_q[(size_t)1024 * KC];
__device__ __half g_Wh_k[(size_t)1024 * KC];
__device__ __half g_Wl_k[(size_t)1024 * KC];
__device__ __half g_Wh_v[(size_t)1024 * KC];
__device__ __half g_Wl_v[(size_t)1024 * KC];
__device__ __half g_Xh_q[(size_t)NB * 1024 * 1024];   // [b][p][i] fp16
__device__ __half g_Xh_k[(size_t)NB * 1024 * 1024];
__device__ __half g_Xh_v[(size_t)NB * 1024 * 1024];
__device__ float g_Qh[NB * NCH * 1024];    // [B,16,t,64]
__device__ float g_Kh[NB * NCH * 1024];
__device__ float g_Vh[NB * NCH * 1024];
__device__ float g_attn[NB * NCH * 1024];  // [B,t,1024]

// ---------------- helpers ---------------------------------------------------
__device__ __forceinline__ uint32_t smem_u32(const void* p) {
    uint32_t a;
    asm("{ .reg .u64 t; cvta.to.shared.u64 t, %1; cvt.u32.u64 %0, t; }"
        : "=r"(a) : "l"(p));
    return a;
}
__device__ __forceinline__ void cp16(uint32_t dst, const void* src, int sz) {
    asm volatile("cp.async.ca.shared.global [%0], [%1], 16, %2;"
                 :: "r"(dst), "l"(src), "r"(sz) : "memory");
}
__device__ __forceinline__ void cp_commit() {
    asm volatile("cp.async.commit_group;" ::: "memory");
}
__device__ __forceinline__ void ldsm_x4(uint32_t* r, uint32_t addr) {
    asm volatile("ldmatrix.sync.aligned.m8n8.x4.shared.b16 {%0,%1,%2,%3}, [%4];"
                 : "=r"(r[0]), "=r"(r[1]), "=r"(r[2]), "=r"(r[3]) : "r"(addr));
}
__device__ __forceinline__ void mma_f16(float* d, const uint32_t* a,
                                        const uint32_t* bb) {
    asm volatile(
        "mma.sync.aligned.m16n8k16.row.col.f32.f16.f16.f32 "
        "{%0,%1,%2,%3}, {%4,%5,%6,%7}, {%8,%9}, {%0,%1,%2,%3};"
        : "+f"(d[0]), "+f"(d[1]), "+f"(d[2]), "+f"(d[3])
        : "r"(a[0]), "r"(a[1]), "r"(a[2]), "r"(a[3]), "r"(bb[0]), "r"(bb[1]));
}

// exp(x) for x <= 0 on the FMA/ALU pipes (no MUFU). Handles -1e9 via clamp
// (result ~1e-38 ~= 0). Max rel error ~2.4e-6 (deg-5 Taylor on [-.5,.5]).
__device__ __forceinline__ float fast_exp(float x) {
    x = fmaxf(x, -87.0f);
    float t = x * 1.4426950408889634f;          // log2(e)
    float z = t + 12582912.0f;                  // 1.5*2^23 round-to-int magic
    int   n = __float_as_int(z) - 0x4B400000;
    float r = t - (z - 12582912.0f);            // r in [-0.5, 0.5]
    float p =          1.3333558146e-3f;
    p = fmaf(p, r, 9.6181291076e-3f);
    p = fmaf(p, r, 5.5504108665e-2f);
    p = fmaf(p, r, 2.4022650696e-1f);
    p = fmaf(p, r, 6.9314718056e-1f);
    p = fmaf(p, r, 1.0f);
    return __int_as_float(__float_as_int(p) + (n << 23));
}

// ---------------------------------------------------------------------------
// Weight prep: W[o,i,tap]*512 -> fp16 hi/lo planes, layout [o][tap*1024 + i]
// ---------------------------------------------------------------------------
__global__ void wprep_kernel(const float* __restrict__ W,
                             __half* __restrict__ Wh, __half* __restrict__ Wl)
{
    int idx = blockIdx.x * 256 + threadIdx.x;      // o*9216 + i*9 + tap
    int tap = idx % 9;
    int rem = idx / 9;
    int i = rem & 1023;
    int o = rem >> 10;
    float v = W[idx] * WSCALE;
    __half hi = __float2half(v);
    __half lo = __float2half(v - __half2float(hi));
    size_t dst = (size_t)o * KC + tap * 1024 + i;
    Wh[dst] = hi;
    Wl[dst] = lo;
}

// ---------------------------------------------------------------------------
// Input prep (smem-tiled transpose): x[b,i,p] -> Xh[b][p][i] fp16
// ---------------------------------------------------------------------------
__global__ __launch_bounds__(256) void xprep_kernel(
    const float* __restrict__ x, __half* __restrict__ Xh)
{
    __shared__ __half sT[64][72];                  // [p][i]
    const int b  = blockIdx.z;
    const int i0 = blockIdx.y * 64;
    const int p0 = blockIdx.x * 64;
    const int tid = threadIdx.x;

    #pragma unroll
    for (int it = 0; it < 16; it++) {
        int idx = tid + it * 256;                  // 4096 elems
        int r = idx >> 6, c = idx & 63;            // i = i0+r, p = p0+c
        sT[c][r] = __float2half(
            x[((size_t)b << 20) + (size_t)(i0 + r) * 1024 + p0 + c]);
    }
    __syncthreads();
    #pragma unroll
    for (int it = 0; it < 2; it++) {
        int w = tid + it * 256;                    // 512 float4 (8 halves)
        int row = w >> 3, c4 = w & 7;
        float4 val = *(const float4*)&sT[row][c4 * 8];
        *(float4*)(Xh + ((size_t)(b * 1024 + p0 + row)) * 1024 +
                   i0 + c4 * 8) = val;
    }
}

// ---------------------------------------------------------------------------
// fp16 2-term split tensor-core conv GEMM, shared-B dual-plane A.
// CTA: 128 oc (M) x 256 px (N), 256 threads, warp grid 2(m)x4(n),
// warp tile 64x64. K = 9216 in 144 chunks of 64; per chunk both A planes
// multiply the SAME B tile (B loaded/fragmented once -> 1.5x fewer HMMA
// than 3-term and ~2.2x less global traffic). 3-stage cp.async ring.
// Output (acc/512 + bias) in head layout [B,16,t=oc,d=p&63].
// ---------------------------------------------------------------------------
__global__ __launch_bounds__(256, 1) void conv_tc_kernel(
    const __half* __restrict__ Wh, const __half* __restrict__ Wl,
    const __half* __restrict__ Xh,
    const float* __restrict__ bias, float* __restrict__ outH)
{
    extern __shared__ __align__(16) __half sm[];
    const int b  = blockIdx.z;
    const int m0 = blockIdx.y * 128;
    const int n0 = blockIdx.x * 256;
    const int tid  = threadIdx.x;
    const int wid  = tid >> 5, lane = tid & 31;
    const int gid  = lane >> 2, tig = lane & 3;
    const int wm   = wid >> 2, wn = wid & 3;       // 2 x 4 warp grid

    const __half* Whb = Wh + (size_t)m0 * KC;
    const __half* Wlb = Wl + (size_t)m0 * KC;
    const __half* Xb  = Xh + ((size_t)b << 20);

    const uint32_t laneA = (uint32_t)(((lane & 15) * SPITCH + 8 * (lane >> 4)) * 2);
    const uint32_t laneB = (uint32_t)((((lane & 7) + 8 * (lane >> 4)) * SPITCH +
                                      8 * ((lane >> 3) & 1)) * 2);
    const uint32_t smBase = smem_u32(sm);

    float acc[4][8][4];
    #pragma unroll
    for (int mt = 0; mt < 4; mt++)
        #pragma unroll
        for (int nt = 0; nt < 8; nt++)
            #pragma unroll
            for (int r = 0; r < 4; r++) acc[mt][nt][r] = 0.f;

    auto load_stage = [&](int s, int st) {
        const int tap = s >> 4, kc = s & 15;       // 16 chunks per tap
        const int koffA = tap * 1024 + kc * 64;
        const int koffB = kc * 64;
        const int dy = tap / 3 - 1, dx = tap % 3 - 1;
        __half* stAh = sm + (size_t)st * STAGE_ELEMS;
        __half* stAl = stAh + 128 * SPITCH;
        __half* stB  = stAh + 256 * SPITCH;
        #pragma unroll
        for (int it = 0; it < 4; it++) {           // A_hi: 1024 cp16
            int idx = tid + it * 256;
            int row = idx >> 3, c = idx & 7;
            cp16(smem_u32(stAh + row * SPITCH + c * 8),
                 Whb + (size_t)row * KC + koffA + c * 8, 16);
        }
        #pragma unroll
        for (int it = 0; it < 4; it++) {           // A_lo: 1024 cp16
            int idx = tid + it * 256;
            int row = idx >> 3, c = idx & 7;
            cp16(smem_u32(stAl + row * SPITCH + c * 8),
                 Wlb + (size_t)row * KC + koffA + c * 8, 16);
        }
        #pragma unroll
        for (int it = 0; it < 8; it++) {           // B: 2048 cp16
            int idx = tid + it * 256;
            int row = idx >> 3, c = idx & 7;
            int p = n0 + row;
            int ys = (p >> 5) + dy, xs = (p & 31) + dx;
            bool ok = ((unsigned)ys < 32u) && ((unsigned)xs < 32u);
            int pp = ok ? (ys * 32 + xs) : 0;
            cp16(smem_u32(stB + row * SPITCH + c * 8),
                 Xb + (size_t)pp * 1024 + koffB + c * 8, ok ? 16 : 0);
        }
    };

    load_stage(0, 0); cp_commit();
    load_stage(1, 1); cp_commit();

    int st = 0;                                    // stage s % 3
    for (int s = 0; s < NSTAGE; s++) {
        asm volatile("cp.async.wait_group 1;" ::: "memory");
        __syncthreads();
        if (s + 2 < NSTAGE) {
            int st2 = st + 2; if (st2 >= 3) st2 -= 3;
            load_stage(s + 2, st2);
        }
        cp_commit();                               // empty groups keep count

        const uint32_t stOff = smBase + (uint32_t)(st * STAGE_BYTES);
        const uint32_t aH = stOff + (uint32_t)(wm * 64 * SPITCH * 2) + laneA;
        const uint32_t aL = aH + OFF_ALO;
        const uint32_t aB = stOff + OFF_B +
                            (uint32_t)(wn * 64 * SPITCH * 2) + laneB;
        #pragma unroll
        for (int kb = 0; kb < 4; kb++) {
            const uint32_t ko = kb * 32;           // 16 fp16 = 32 B
            uint32_t bf4[4][4];
            #pragma unroll
            for (int p = 0; p < 4; p++)
                ldsm_x4(bf4[p], aB + (uint32_t)(p * 16 * SPITCH * 2) + ko);
            uint32_t afH[4][4], afL[4][4];
            #pragma unroll
            for (int mt = 0; mt < 4; mt++) {
                ldsm_x4(afH[mt], aH + (uint32_t)(mt * 16 * SPITCH * 2) + ko);
                ldsm_x4(afL[mt], aL + (uint32_t)(mt * 16 * SPITCH * 2) + ko);
            }
            #pragma unroll
            for (int mt = 0; mt < 4; mt++)
                #pragma unroll
                for (int p = 0; p < 4; p++) {
                    mma_f16(acc[mt][2 * p + 0], afH[mt], &bf4[p][0]);
                    mma_f16(acc[mt][2 * p + 1], afH[mt], &bf4[p][2]);
                    mma_f16(acc[mt][2 * p + 0], afL[mt], &bf4[p][0]);
                    mma_f16(acc[mt][2 * p + 1], afL[mt], &bf4[p][2]);
                }
        }
        if (++st >= 3) st -= 3;
    }

    // epilogue -> head layout  outH[((b*16 + p>>6)*1024 + oc)*64 + (p&63)]
    #pragma unroll
    for (int mt = 0; mt < 4; mt++) {
        int r = m0 + wm * 64 + mt * 16 + gid;
        float bv0 = bias[r], bv1 = bias[r + 8];
        #pragma unroll
        for (int nt = 0; nt < 8; nt++) {
            int p = n0 + wn * 64 + nt * 8 + tig * 2;
            size_t base = ((size_t)b * 16 + (p >> 6)) * 1024;
            size_t i00 = (base + r) * 64 + (p & 63);
            size_t i10 = (base + r + 8) * 64 + (p & 63);
            outH[i00]     = acc[mt][nt][0] * INV_WSCALE + bv0;
            outH[i00 + 1] = acc[mt][nt][1] * INV_WSCALE + bv0;
            outH[i10]     = acc[mt][nt][2] * INV_WSCALE + bv1;
            outH[i10 + 1] = acc[mt][nt][3] * INV_WSCALE + bv1;
        }
    }
}

// ---------------------------------------------------------------------------
// Streaming-softmax attention; exp moved off MUFU onto the FMA pipe.
// ---------------------------------------------------------------------------
__global__ __launch_bounds__(256) void attn_kernel(
    const float* __restrict__ Qh, const float* __restrict__ Kh,
    const float* __restrict__ Vh, const int* __restrict__ mask,
    float* __restrict__ out)
{
    extern __shared__ float smf[];
    float* sQ = smf;
    float* sK = smf + 64 * 65;
    float* sV = smf + 2 * 64 * 65;
    float* sP = smf + 3 * 64 * 65;

    const int b = blockIdx.z, h = blockIdx.y, t0 = blockIdx.x * 64;
    const int tid = threadIdx.x, tx = tid & 15, ty = tid >> 4;

    const size_t bh = ((size_t)b * 16 + h) * 1024 * 64;
    const float* Qb = Qh + bh;
    const float* Kb = Kh + bh;
    const float* Vb = Vh + bh;

    for (int idx = tid; idx < 64 * 64; idx += 256) {
        int r = idx >> 6, c = idx & 63;
        sQ[r * 65 + c] = Qb[(size_t)(t0 + r) * 64 + c] * 0.125f;
    }

    float m_i[4], l_i[4], O[4][4];
    #pragma unroll
    for (int mm = 0; mm < 4; mm++) {
        m_i[mm] = -1e30f; l_i[mm] = 0.f;
        #pragma unroll
        for (int nn = 0; nn < 4; nn++) O[mm][nn] = 0.f;
    }

    for (int s0 = 0; s0 < 1024; s0 += 64) {
        __syncthreads();
        for (int idx = tid; idx < 64 * 64; idx += 256) {
            int r = idx >> 6, c = idx & 63;
            sK[r * 65 + c] = Kb[(size_t)(s0 + r) * 64 + c];
            sV[r * 65 + c] = Vb[(size_t)(s0 + r) * 64 + c];
        }
        __syncthreads();

        float S[4][4];
        #pragma unroll
        for (int mm = 0; mm < 4; mm++)
            #pragma unroll
            for (int nn = 0; nn < 4; nn++) S[mm][nn] = 0.f;

        #pragma unroll 8
        for (int k = 0; k < 64; k++) {
            float a[4], bb[4];
            #pragma unroll
            for (int mm = 0; mm < 4; mm++) a[mm] = sQ[(ty * 4 + mm) * 65 + k];
            #pragma unroll
            for (int nn = 0; nn < 4; nn++) bb[nn] = sK[(tx + nn * 16) * 65 + k];
            #pragma unroll
            for (int mm = 0; mm < 4; mm++)
                #pragma unroll
                for (int nn = 0; nn < 4; nn++) S[mm][nn] += a[mm] * bb[nn];
        }

        #pragma unroll
        for (int mm = 0; mm < 4; mm++) {
            const int* mrow = mask + ((size_t)b * 1024 + t0 + ty * 4 + mm) * 1024 + s0;
            #pragma unroll
            for (int nn = 0; nn < 4; nn++)
                if (mrow[tx + nn * 16] == 0) S[mm][nn] = -1e9f;
        }

        #pragma unroll
        for (int mm = 0; mm < 4; mm++) {
            float mx = fmaxf(fmaxf(S[mm][0], S[mm][1]), fmaxf(S[mm][2], S[mm][3]));
            #pragma unroll
            for (int off = 8; off >= 1; off >>= 1)
                mx = fmaxf(mx, __shfl_xor_sync(0xffffffffu, mx, off));
            float mnew = fmaxf(m_i[mm], mx);
            float corr = fast_exp(m_i[mm] - mnew);
            float rs = 0.f;
            #pragma unroll
            for (int nn = 0; nn < 4; nn++) {
                float p = fast_exp(S[mm][nn] - mnew);
                S[mm][nn] = p;
                rs += p;
            }
            #pragma unroll
            for (int off = 8; off >= 1; off >>= 1)
                rs += __shfl_xor_sync(0xffffffffu, rs, off);
            l_i[mm] = l_i[mm] * corr + rs;
            m_i[mm] = mnew;
            #pragma unroll
            for (int nn = 0; nn < 4; nn++) O[mm][nn] *= corr;
            #pragma unroll
            for (int nn = 0; nn < 4; nn++)
                sP[(ty * 4 + mm) * 65 + tx + nn * 16] = S[mm][nn];
        }
        __syncthreads();

        #pragma unroll 8
        for (int k = 0; k < 64; k++) {
            float a[4], bb[4];
            #pragma unroll
            for (int mm = 0; mm < 4; mm++) a[mm] = sP[(ty * 4 + mm) * 65 + k];
            #pragma unroll
            for (int nn = 0; nn < 4; nn++) bb[nn] = sV[k * 65 + tx + nn * 16];
            #pragma unroll
            for (int mm = 0; mm < 4; mm++)
                #pragma unroll
                for (int nn = 0; nn < 4; nn++) O[mm][nn] += a[mm] * bb[nn];
        }
    }

    #pragma unroll
    for (int mm = 0; mm < 4; mm++) {
        float inv = 1.f / l_i[mm];
        int t = t0 + ty * 4 + mm;
        #pragma unroll
        for (int nn = 0; nn < 4; nn++)
            out[((size_t)b * 1024 + t) * 1024 + h * 64 + tx + nn * 16] = O[mm][nn] * inv;
    }
}

// ---------------------------------------------------------------------------
// Output projection (unchanged).
// ---------------------------------------------------------------------------
__global__ __launch_bounds__(256) void proj_kernel(
    const float* __restrict__ A, const float* __restrict__ Wo,
    const float* __restrict__ bo, float* __restrict__ out)
{
    __shared__ float sA[64][17];
    __shared__ float sB[64][17];
    const int m0 = blockIdx.y * 64, n0 = blockIdx.x * 64;
    const int tid = threadIdx.x, tx = tid & 15, ty = tid >> 4;

    float acc[4][4];
    #pragma unroll
    for (int mm = 0; mm < 4; mm++)
        #pragma unroll
        for (int nn = 0; nn < 4; nn++) acc[mm][nn] = 0.f;

    for (int k0 = 0; k0 < 1024; k0 += 16) {
        for (int idx = tid; idx < 1024; idx += 256) {
            int r = idx >> 4, c = idx & 15;
            sA[r][c] = A[(size_t)(m0 + r) * 1024 + k0 + c];
            sB[r][c] = Wo[(size_t)(n0 + r) * 1024 + k0 + c];
        }
        __syncthreads();
        #pragma unroll
        for (int kk = 0; kk < 16; kk++) {
            float a[4], bb[4];
            #pragma unroll
            for (int mm = 0; mm < 4; mm++) a[mm] = sA[ty * 4 + mm][kk];
            #pragma unroll
            for (int nn = 0; nn < 4; nn++) bb[nn] = sB[tx + nn * 16][kk];
            #pragma unroll
            for (int mm = 0; mm < 4; mm++)
                #pragma unroll
                for (int nn = 0; nn < 4; nn++) acc[mm][nn] += a[mm] * bb[nn];
        }
        __syncthreads();
    }

    #pragma unroll
    for (int mm = 0; mm < 4; mm++)
        #pragma unroll
        for (int nn = 0; nn < 4; nn++)
            out[(size_t)(m0 + ty * 4 + mm) * 1024 + n0 + tx + nn * 16] =
                acc[mm][nn] + bo[n0 + tx + nn * 16];
}

// ---------------------------------------------------------------------------
extern "C" void kernel_launch(void* const* d_in, const int* in_sizes, int n_in,
                              void* d_out, int out_size)
{
    const float* q   = (const float*)d_in[0];
    const float* k   = (const float*)d_in[1];
    const float* v   = (const float*)d_in[2];
    const float* Wq  = (const float*)d_in[3];
    const float* bq  = (const float*)d_in[4];
    const float* Wk  = (const float*)d_in[5];
    const float* bk  = (const float*)d_in[6];
    const float* Wv  = (const float*)d_in[7];
    const float* bv  = (const float*)d_in[8];
    const float* Wo  = (const float*)d_in[9];
    const float* bo  = (const float*)d_in[10];
    const int*   msk = (const int*)d_in[11];
    float* out = (float*)d_out;

    __half *whq, *wlq, *whk, *wlk, *whv, *wlv, *xhq, *xhk, *xhv;
    float *qh, *kh, *vh, *attn;
    cudaGetSymbolAddress((void**)&whq, g_Wh_q);
    cudaGetSymbolAddress((void**)&wlq, g_Wl_q);
    cudaGetSymbolAddress((void**)&whk, g_Wh_k);
    cudaGetSymbolAddress((void**)&wlk, g_Wl_k);
    cudaGetSymbolAddress((void**)&whv, g_Wh_v);
    cudaGetSymbolAddress((void**)&wlv, g_Wl_v);
    cudaGetSymbolAddress((void**)&xhq, g_Xh_q);
    cudaGetSymbolAddress((void**)&xhk, g_Xh_k);
    cudaGetSymbolAddress((void**)&xhv, g_Xh_v);
    cudaGetSymbolAddress((void**)&qh,  g_Qh);
    cudaGetSymbolAddress((void**)&kh,  g_Kh);
    cudaGetSymbolAddress((void**)&vh,  g_Vh);
    cudaGetSymbolAddress((void**)&attn, g_attn);

    // 1) fp16 2-term prep
    wprep_kernel<<<(1024 * 1024 * 9) / 256, 256>>>(Wq, whq, wlq);
    wprep_kernel<<<(1024 * 1024 * 9) / 256, 256>>>(Wk, whk, wlk);
    wprep_kernel<<<(1024 * 1024 * 9) / 256, 256>>>(Wv, whv, wlv);
    dim3 xg(16, 16, NB);
    xprep_kernel<<<xg, 256>>>(q, xhq);
    xprep_kernel<<<xg, 256>>>(k, xhk);
    xprep_kernel<<<xg, 256>>>(v, xhv);

    // 2) tensor-core convs -> head layout (3-stage ring: 221184 B smem)
    const int conv_smem = 3 * STAGE_BYTES;
    cudaFuncSetAttribute(conv_tc_kernel,
                         cudaFuncAttributeMaxDynamicSharedMemorySize, conv_smem);
    dim3 cg(4, 8, NB);
    conv_tc_kernel<<<cg, 256, conv_smem>>>(whq, wlq, xhq, bq, qh);
    conv_tc_kernel<<<cg, 256, conv_smem>>>(whk, wlk, xhk, bk, kh);
    conv_tc_kernel<<<cg, 256, conv_smem>>>(whv, wlv, xhv, bv, vh);

    // 3) attention
    cudaFuncSetAttribute(attn_kernel,
                         cudaFuncAttributeMaxDynamicSharedMemorySize, 66560);
    attn_kernel<<<dim3(16, NHEAD, NB), 256, 66560>>>(qh, kh, vh, msk, attn);

    // 4) projection
    proj_kernel<<<dim3(16, 128), 256>>>(attn, Wo, bo, out);
}

// round 12
// speedup vs baseline: 1.8041x; 1.0007x over previous
#include <cuda_runtime.h>
#include <cuda_fp16.h>
#include <cstdint>

// ---------------------------------------------------------------------------
// MultiHeadAttn: conv3x3(q/k/v) via 2-term fp16-split mma.m16n8k16 implicit
// GEMM (shared-B dual-plane A, 64x64 warp tiles, ldmatrix, 3-stage cp.async
// ring) -> split heads -> masked softmax attention (FMA-pipe exp) -> proj.
// B=8, C=1024 (tokens), H=W=32 (spatial=1024), heads=16, d=64.
// Split: w*x = (w_hi + w_lo)*x, w_hi/w_lo fp16 (pre-scaled by 512 to avoid
// fp16 subnormals in w_lo), x fp16. One B tile serves both A planes.
// ---------------------------------------------------------------------------

#define NCH   1024
#define NB    8
#define NHEAD 16
#define KC    9216            // 9 taps * 1024 channels (per A plane)
#define NSTAGE 144            // 9216 / 64
#define SPITCH 72             // fp16 elems per smem row (64 + pad), 144B
#define STAGE_ELEMS ((128 + 128 + 256) * SPITCH)   // A_hi + A_lo + B
#define STAGE_BYTES (STAGE_ELEMS * 2)              // 73728 B
#define OFF_ALO (128 * SPITCH * 2)
#define OFF_B   (256 * SPITCH * 2)
#define WSCALE   512.0f
#define INV_WSCALE 0.001953125f

// ---------------- device scratch (no allocation allowed) -------------------
__device__ __half g_Wh_q[(size_t)1024 * KC];
__device__ __half g_Wl_q[(size_t)1024 * KC];
__device__ __half g_Wh_k[(size_t)1024 * KC];
__device__ __half g_Wl_k[(size_t)1024 * KC];
__device__ __half g_Wh_v[(size_t)1024 * KC];
__device__ __half g_Wl_v[(size_t)1024 * KC];
__device__ __half g_Xh_q[(size_t)NB * 1024 * 1024];   // [b][p][i] fp16
__device__ __half g_Xh_k[(size_t)NB * 1024 * 1024];
__device__ __half g_Xh_v[(size_t)NB * 1024 * 1024];
__device__ float g_Qh[NB * NCH * 1024];    // [B,16,t,64]
__device__ float g_Kh[NB * NCH * 1024];
__device__ float g_Vh[NB * NCH * 1024];
__device__ float g_attn[NB * NCH * 1024];  // [B,t,1024]

// ---------------- helpers ---------------------------------------------------
__device__ __forceinline__ uint32_t smem_u32(const void* p) {
    uint32_t a;
    asm("{ .reg .u64 t; cvta.to.shared.u64 t, %1; cvt.u32.u64 %0, t; }"
        : "=r"(a) : "l"(p));
    return a;
}
__device__ __forceinline__ void cp16(uint32_t dst, const void* src, int sz) {
    asm volatile("cp.async.ca.shared.global [%0], [%1], 16, %2;"
                 :: "r"(dst), "l"(src), "r"(sz) : "memory");
}
__device__ __forceinline__ void cp_commit() {
    asm volatile("cp.async.commit_group;" ::: "memory");
}
__device__ __forceinline__ void ldsm_x4(uint32_t* r, uint32_t addr) {
    asm volatile("ldmatrix.sync.aligned.m8n8.x4.shared.b16 {%0,%1,%2,%3}, [%4];"
                 : "=r"(r[0]), "=r"(r[1]), "=r"(r[2]), "=r"(r[3]) : "r"(addr));
}
__device__ __forceinline__ void mma_f16(float* d, const uint32_t* a,
                                        const uint32_t* bb) {
    asm volatile(
        "mma.sync.aligned.m16n8k16.row.col.f32.f16.f16.f32 "
        "{%0,%1,%2,%3}, {%4,%5,%6,%7}, {%8,%9}, {%0,%1,%2,%3};"
        : "+f"(d[0]), "+f"(d[1]), "+f"(d[2]), "+f"(d[3])
        : "r"(a[0]), "r"(a[1]), "r"(a[2]), "r"(a[3]), "r"(bb[0]), "r"(bb[1]));
}

// exp(x) for x <= 0 on the FMA/ALU pipes (no MUFU). Handles -1e9 via clamp
// (result ~1e-38 ~= 0). Max rel error ~2.4e-6 (deg-5 Taylor on [-.5,.5]).
__device__ __forceinline__ float fast_exp(float x) {
    x = fmaxf(x, -87.0f);
    float t = x * 1.4426950408889634f;          // log2(e)
    float z = t + 12582912.0f;                  // 1.5*2^23 round-to-int magic
    int   n = __float_as_int(z) - 0x4B400000;
    float r = t - (z - 12582912.0f);            // r in [-0.5, 0.5]
    float p =          1.3333558146e-3f;
    p = fmaf(p, r, 9.6181291076e-3f);
    p = fmaf(p, r, 5.5504108665e-2f);
    p = fmaf(p, r, 2.4022650696e-1f);
    p = fmaf(p, r, 6.9314718056e-1f);
    p = fmaf(p, r, 1.0f);
    return __int_as_float(__float_as_int(p) + (n << 23));
}

// ---------------------------------------------------------------------------
// Weight prep: W[o,i,tap]*512 -> fp16 hi/lo planes, layout [o][tap*1024 + i]
// ---------------------------------------------------------------------------
__global__ void wprep_kernel(const float* __restrict__ W,
                             __half* __restrict__ Wh, __half* __restrict__ Wl)
{
    int idx = blockIdx.x * 256 + threadIdx.x;      // o*9216 + i*9 + tap
    int tap = idx % 9;
    int rem = idx / 9;
    int i = rem & 1023;
    int o = rem >> 10;
    float v = W[idx] * WSCALE;
    __half hi = __float2half(v);
    __half lo = __float2half(v - __half2float(hi));
    size_t dst = (size_t)o * KC + tap * 1024 + i;
    Wh[dst] = hi;
    Wl[dst] = lo;
}

// ---------------------------------------------------------------------------
// Input prep (smem-tiled transpose): x[b,i,p] -> Xh[b][p][i] fp16
// ---------------------------------------------------------------------------
__global__ __launch_bounds__(256) void xprep_kernel(
    const float* __restrict__ x, __half* __restrict__ Xh)
{
    __shared__ __half sT[64][72];                  // [p][i]
    const int b  = blockIdx.z;
    const int i0 = blockIdx.y * 64;
    const int p0 = blockIdx.x * 64;
    const int tid = threadIdx.x;

    #pragma unroll
    for (int it = 0; it < 16; it++) {
        int idx = tid + it * 256;                  // 4096 elems
        int r = idx >> 6, c = idx & 63;            // i = i0+r, p = p0+c
        sT[c][r] = __float2half(
            x[((size_t)b << 20) + (size_t)(i0 + r) * 1024 + p0 + c]);
    }
    __syncthreads();
    #pragma unroll
    for (int it = 0; it < 2; it++) {
        int w = tid + it * 256;                    // 512 float4 (8 halves)
        int row = w >> 3, c4 = w & 7;
        float4 val = *(const float4*)&sT[row][c4 * 8];
        *(float4*)(Xh + ((size_t)(b * 1024 + p0 + row)) * 1024 +
                   i0 + c4 * 8) = val;
    }
}

// ---------------------------------------------------------------------------
// fp16 2-term split tensor-core conv GEMM, shared-B dual-plane A.
// CTA: 128 oc (M) x 256 px (N), 256 threads, warp grid 2(m)x4(n),
// warp tile 64x64. K = 9216 in 144 chunks of 64; per chunk both A planes
// multiply the SAME B tile (B loaded/fragmented once -> 1.5x fewer HMMA
// than 3-term and ~2.2x less global traffic). 3-stage cp.async ring.
// Output (acc/512 + bias) in head layout [B,16,t=oc,d=p&63].
// ---------------------------------------------------------------------------
__global__ __launch_bounds__(256, 1) void conv_tc_kernel(
    const __half* __restrict__ Wh, const __half* __restrict__ Wl,
    const __half* __restrict__ Xh,
    const float* __restrict__ bias, float* __restrict__ outH)
{
    extern __shared__ __align__(16) __half sm[];
    const int b  = blockIdx.z;
    const int m0 = blockIdx.y * 128;
    const int n0 = blockIdx.x * 256;
    const int tid  = threadIdx.x;
    const int wid  = tid >> 5, lane = tid & 31;
    const int gid  = lane >> 2, tig = lane & 3;
    const int wm   = wid >> 2, wn = wid & 3;       // 2 x 4 warp grid

    const __half* Whb = Wh + (size_t)m0 * KC;
    const __half* Wlb = Wl + (size_t)m0 * KC;
    const __half* Xb  = Xh + ((size_t)b << 20);

    const uint32_t laneA = (uint32_t)(((lane & 15) * SPITCH + 8 * (lane >> 4)) * 2);
    const uint32_t laneB = (uint32_t)((((lane & 7) + 8 * (lane >> 4)) * SPITCH +
                                      8 * ((lane >> 3) & 1)) * 2);
    const uint32_t smBase = smem_u32(sm);

    float acc[4][8][4];
    #pragma unroll
    for (int mt = 0; mt < 4; mt++)
        #pragma unroll
        for (int nt = 0; nt < 8; nt++)
            #pragma unroll
            for (int r = 0; r < 4; r++) acc[mt][nt][r] = 0.f;

    auto load_stage = [&](int s, int st) {
        const int tap = s >> 4, kc = s & 15;       // 16 chunks per tap
        const int koffA = tap * 1024 + kc * 64;
        const int koffB = kc * 64;
        const int dy = tap / 3 - 1, dx = tap % 3 - 1;
        __half* stAh = sm + (size_t)st * STAGE_ELEMS;
        __half* stAl = stAh + 128 * SPITCH;
        __half* stB  = stAh + 256 * SPITCH;
        #pragma unroll
        for (int it = 0; it < 4; it++) {           // A_hi: 1024 cp16
            int idx = tid + it * 256;
            int row = idx >> 3, c = idx & 7;
            cp16(smem_u32(stAh + row * SPITCH + c * 8),
                 Whb + (size_t)row * KC + koffA + c * 8, 16);
        }
        #pragma unroll
        for (int it = 0; it < 4; it++) {           // A_lo: 1024 cp16
            int idx = tid + it * 256;
            int row = idx >> 3, c = idx & 7;
            cp16(smem_u32(stAl + row * SPITCH + c * 8),
                 Wlb + (size_t)row * KC + koffA + c * 8, 16);
        }
        #pragma unroll
        for (int it = 0; it < 8; it++) {           // B: 2048 cp16
            int idx = tid + it * 256;
            int row = idx >> 3, c = idx & 7;
            int p = n0 + row;
            int ys = (p >> 5) + dy, xs = (p & 31) + dx;
            bool ok = ((unsigned)ys < 32u) && ((unsigned)xs < 32u);
            int pp = ok ? (ys * 32 + xs) : 0;
            cp16(smem_u32(stB + row * SPITCH + c * 8),
                 Xb + (size_t)pp * 1024 + koffB + c * 8, ok ? 16 : 0);
        }
    };

    load_stage(0, 0); cp_commit();
    load_stage(1, 1); cp_commit();

    int st = 0;                                    // stage s % 3
    for (int s = 0; s < NSTAGE; s++) {
        asm volatile("cp.async.wait_group 1;" ::: "memory");
        __syncthreads();
        if (s + 2 < NSTAGE) {
            int st2 = st + 2; if (st2 >= 3) st2 -= 3;
            load_stage(s + 2, st2);
        }
        cp_commit();                               // empty groups keep count

        const uint32_t stOff = smBase + (uint32_t)(st * STAGE_BYTES);
        const uint32_t aH = stOff + (uint32_t)(wm * 64 * SPITCH * 2) + laneA;
        const uint32_t aL = aH + OFF_ALO;
        const uint32_t aB = stOff + OFF_B +
                            (uint32_t)(wn * 64 * SPITCH * 2) + laneB;
        #pragma unroll
        for (int kb = 0; kb < 4; kb++) {
            const uint32_t ko = kb * 32;           // 16 fp16 = 32 B
            uint32_t bf4[4][4];
            #pragma unroll
            for (int p = 0; p < 4; p++)
                ldsm_x4(bf4[p], aB + (uint32_t)(p * 16 * SPITCH * 2) + ko);
            uint32_t afH[4][4], afL[4][4];
            #pragma unroll
            for (int mt = 0; mt < 4; mt++) {
                ldsm_x4(afH[mt], aH + (uint32_t)(mt * 16 * SPITCH * 2) + ko);
                ldsm_x4(afL[mt], aL + (uint32_t)(mt * 16 * SPITCH * 2) + ko);
            }
            #pragma unroll
            for (int mt = 0; mt < 4; mt++)
                #pragma unroll
                for (int p = 0; p < 4; p++) {
                    mma_f16(acc[mt][2 * p + 0], afH[mt], &bf4[p][0]);
                    mma_f16(acc[mt][2 * p + 1], afH[mt], &bf4[p][2]);
                    mma_f16(acc[mt][2 * p + 0], afL[mt], &bf4[p][0]);
                    mma_f16(acc[mt][2 * p + 1], afL[mt], &bf4[p][2]);
                }
        }
        if (++st >= 3) st -= 3;
    }

    // epilogue -> head layout  outH[((b*16 + p>>6)*1024 + oc)*64 + (p&63)]
    #pragma unroll
    for (int mt = 0; mt < 4; mt++) {
        int r = m0 + wm * 64 + mt * 16 + gid;
        float bv0 = bias[r], bv1 = bias[r + 8];
        #pragma unroll
        for (int nt = 0; nt < 8; nt++) {
            int p = n0 + wn * 64 + nt * 8 + tig * 2;
            size_t base = ((size_t)b * 16 + (p >> 6)) * 1024;
            size_t i00 = (base + r) * 64 + (p & 63);
            size_t i10 = (base + r + 8) * 64 + (p & 63);
            outH[i00]     = acc[mt][nt][0] * INV_WSCALE + bv0;
            outH[i00 + 1] = acc[mt][nt][1] * INV_WSCALE + bv0;
            outH[i10]     = acc[mt][nt][2] * INV_WSCALE + bv1;
            outH[i10 + 1] = acc[mt][nt][3] * INV_WSCALE + bv1;
        }
    }
}

// ---------------------------------------------------------------------------
// Streaming-softmax attention; exp moved off MUFU onto the FMA pipe.
// ---------------------------------------------------------------------------
__global__ __launch_bounds__(256) void attn_kernel(
    const float* __restrict__ Qh, const float* __restrict__ Kh,
    const float* __restrict__ Vh, const int* __restrict__ mask,
    float* __restrict__ out)
{
    extern __shared__ float smf[];
    float* sQ = smf;
    float* sK = smf + 64 * 65;
    float* sV = smf + 2 * 64 * 65;
    float* sP = smf + 3 * 64 * 65;

    const int b = blockIdx.z, h = blockIdx.y, t0 = blockIdx.x * 64;
    const int tid = threadIdx.x, tx = tid & 15, ty = tid >> 4;

    const size_t bh = ((size_t)b * 16 + h) * 1024 * 64;
    const float* Qb = Qh + bh;
    const float* Kb = Kh + bh;
    const float* Vb = Vh + bh;

    for (int idx = tid; idx < 64 * 64; idx += 256) {
        int r = idx >> 6, c = idx & 63;
        sQ[r * 65 + c] = Qb[(size_t)(t0 + r) * 64 + c] * 0.125f;
    }

    float m_i[4], l_i[4], O[4][4];
    #pragma unroll
    for (int mm = 0; mm < 4; mm++) {
        m_i[mm] = -1e30f; l_i[mm] = 0.f;
        #pragma unroll
        for (int nn = 0; nn < 4; nn++) O[mm][nn] = 0.f;
    }

    for (int s0 = 0; s0 < 1024; s0 += 64) {
        __syncthreads();
        for (int idx = tid; idx < 64 * 64; idx += 256) {
            int r = idx >> 6, c = idx & 63;
            sK[r * 65 + c] = Kb[(size_t)(s0 + r) * 64 + c];
            sV[r * 65 + c] = Vb[(size_t)(s0 + r) * 64 + c];
        }
        __syncthreads();

        float S[4][4];
        #pragma unroll
        for (int mm = 0; mm < 4; mm++)
            #pragma unroll
            for (int nn = 0; nn < 4; nn++) S[mm][nn] = 0.f;

        #pragma unroll 8
        for (int k = 0; k < 64; k++) {
            float a[4], bb[4];
            #pragma unroll
            for (int mm = 0; mm < 4; mm++) a[mm] = sQ[(ty * 4 + mm) * 65 + k];
            #pragma unroll
            for (int nn = 0; nn < 4; nn++) bb[nn] = sK[(tx + nn * 16) * 65 + k];
            #pragma unroll
            for (int mm = 0; mm < 4; mm++)
                #pragma unroll
                for (int nn = 0; nn < 4; nn++) S[mm][nn] += a[mm] * bb[nn];
        }

        #pragma unroll
        for (int mm = 0; mm < 4; mm++) {
            const int* mrow = mask + ((size_t)b * 1024 + t0 + ty * 4 + mm) * 1024 + s0;
            #pragma unroll
            for (int nn = 0; nn < 4; nn++)
                if (mrow[tx + nn * 16] == 0) S[mm][nn] = -1e9f;
        }

        #pragma unroll
        for (int mm = 0; mm < 4; mm++) {
            float mx = fmaxf(fmaxf(S[mm][0], S[mm][1]), fmaxf(S[mm][2], S[mm][3]));
            #pragma unroll
            for (int off = 8; off >= 1; off >>= 1)
                mx = fmaxf(mx, __shfl_xor_sync(0xffffffffu, mx, off));
            float mnew = fmaxf(m_i[mm], mx);
            float corr = fast_exp(m_i[mm] - mnew);
            float rs = 0.f;
            #pragma unroll
            for (int nn = 0; nn < 4; nn++) {
                float p = fast_exp(S[mm][nn] - mnew);
                S[mm][nn] = p;
                rs += p;
            }
            #pragma unroll
            for (int off = 8; off >= 1; off >>= 1)
                rs += __shfl_xor_sync(0xffffffffu, rs, off);
            l_i[mm] = l_i[mm] * corr + rs;
            m_i[mm] = mnew;
            #pragma unroll
            for (int nn = 0; nn < 4; nn++) O[mm][nn] *= corr;
            #pragma unroll
            for (int nn = 0; nn < 4; nn++)
                sP[(ty * 4 + mm) * 65 + tx + nn * 16] = S[mm][nn];
        }
        __syncthreads();

        #pragma unroll 8
        for (int k = 0; k < 64; k++) {
            float a[4], bb[4];
            #pragma unroll
            for (int mm = 0; mm < 4; mm++) a[mm] = sP[(ty * 4 + mm) * 65 + k];
            #pragma unroll
            for (int nn = 0; nn < 4; nn++) bb[nn] = sV[k * 65 + tx + nn * 16];
            #pragma unroll
            for (int mm = 0; mm < 4; mm++)
                #pragma unroll
                for (int nn = 0; nn < 4; nn++) O[mm][nn] += a[mm] * bb[nn];
        }
    }

    #pragma unroll
    for (int mm = 0; mm < 4; mm++) {
        float inv = 1.f / l_i[mm];
        int t = t0 + ty * 4 + mm;
        #pragma unroll
        for (int nn = 0; nn < 4; nn++)
            out[((size_t)b * 1024 + t) * 1024 + h * 64 + tx + nn * 16] = O[mm][nn] * inv;
    }
}

// ---------------------------------------------------------------------------
// Output projection (unchanged).
// ---------------------------------------------------------------------------
__global__ __launch_bounds__(256) void proj_kernel(
    const float* __restrict__ A, const float* __restrict__ Wo,
    const float* __restrict__ bo, float* __restrict__ out)
{
    __shared__ float sA[64][17];
    __shared__ float sB[64][17];
    const int m0 = blockIdx.y * 64, n0 = blockIdx.x * 64;
    const int tid = threadIdx.x, tx = tid & 15, ty = tid >> 4;

    float acc[4][4];
    #pragma unroll
    for (int mm = 0; mm < 4; mm++)
        #pragma unroll
        for (int nn = 0; nn < 4; nn++) acc[mm][nn] = 0.f;

    for (int k0 = 0; k0 < 1024; k0 += 16) {
        for (int idx = tid; idx < 1024; idx += 256) {
            int r = idx >> 4, c = idx & 15;
            sA[r][c] = A[(size_t)(m0 + r) * 1024 + k0 + c];
            sB[r][c] = Wo[(size_t)(n0 + r) * 1024 + k0 + c];
        }
        __syncthreads();
        #pragma unroll
        for (int kk = 0; kk < 16; kk++) {
            float a[4], bb[4];
            #pragma unroll
            for (int mm = 0; mm < 4; mm++) a[mm] = sA[ty * 4 + mm][kk];
            #pragma unroll
            for (int nn = 0; nn < 4; nn++) bb[nn] = sB[tx + nn * 16][kk];
            #pragma unroll
            for (int mm = 0; mm < 4; mm++)
                #pragma unroll
                for (int nn = 0; nn < 4; nn++) acc[mm][nn] += a[mm] * bb[nn];
        }
        __syncthreads();
    }

    #pragma unroll
    for (int mm = 0; mm < 4; mm++)
        #pragma unroll
        for (int nn = 0; nn < 4; nn++)
            out[(size_t)(m0 + ty * 4 + mm) * 1024 + n0 + tx + nn * 16] =
                acc[mm][nn] + bo[n0 + tx + nn * 16];
}

// ---------------------------------------------------------------------------
extern "C" void kernel_launch(void* const* d_in, const int* in_sizes, int n_in,
                              void* d_out, int out_size)
{
    const float* q   = (const float*)d_in[0];
    const float* k   = (const float*)d_in[1];
    const float* v   = (const float*)d_in[2];
    const float* Wq  = (const float*)d_in[3];
    const float* bq  = (const float*)d_in[4];
    const float* Wk  = (const float*)d_in[5];
    const float* bk  = (const float*)d_in[6];
    const float* Wv  = (const float*)d_in[7];
    const float* bv  = (const float*)d_in[8];
    const float* Wo  = (const float*)d_in[9];
    const float* bo  = (const float*)d_in[10];
    const int*   msk = (const int*)d_in[11];
    float* out = (float*)d_out;

    __half *whq, *wlq, *whk, *wlk, *whv, *wlv, *xhq, *xhk, *xhv;
    float *qh, *kh, *vh, *attn;
    cudaGetSymbolAddress((void**)&whq, g_Wh_q);
    cudaGetSymbolAddress((void**)&wlq, g_Wl_q);
    cudaGetSymbolAddress((void**)&whk, g_Wh_k);
    cudaGetSymbolAddress((void**)&wlk, g_Wl_k);
    cudaGetSymbolAddress((void**)&whv, g_Wh_v);
    cudaGetSymbolAddress((void**)&wlv, g_Wl_v);
    cudaGetSymbolAddress((void**)&xhq, g_Xh_q);
    cudaGetSymbolAddress((void**)&xhk, g_Xh_k);
    cudaGetSymbolAddress((void**)&xhv, g_Xh_v);
    cudaGetSymbolAddress((void**)&qh,  g_Qh);
    cudaGetSymbolAddress((void**)&kh,  g_Kh);
    cudaGetSymbolAddress((void**)&vh,  g_Vh);
    cudaGetSymbolAddress((void**)&attn, g_attn);

    // 1) fp16 2-term prep
    wprep_kernel<<<(1024 * 1024 * 9) / 256, 256>>>(Wq, whq, wlq);
    wprep_kernel<<<(1024 * 1024 * 9) / 256, 256>>>(Wk, whk, wlk);
    wprep_kernel<<<(1024 * 1024 * 9) / 256, 256>>>(Wv, whv, wlv);
    dim3 xg(16, 16, NB);
    xprep_kernel<<<xg, 256>>>(q, xhq);
    xprep_kernel<<<xg, 256>>>(k, xhk);
    xprep_kernel<<<xg, 256>>>(v, xhv);

    // 2) tensor-core convs -> head layout (3-stage ring: 221184 B smem)
    const int conv_smem = 3 * STAGE_BYTES;
    cudaFuncSetAttribute(conv_tc_kernel,
                         cudaFuncAttributeMaxDynamicSharedMemorySize, conv_smem);
    dim3 cg(4, 8, NB);
    conv_tc_kernel<<<cg, 256, conv_smem>>>(whq, wlq, xhq, bq, qh);
    conv_tc_kernel<<<cg, 256, conv_smem>>>(whk, wlk, xhk, bk, kh);
    conv_tc_kernel<<<cg, 256, conv_smem>>>(whv, wlv, xhv, bv, vh);

    // 3) attention
    cudaFuncSetAttribute(attn_kernel,
                         cudaFuncAttributeMaxDynamicSharedMemorySize, 66560);
    attn_kernel<<<dim3(16, NHEAD, NB), 256, 66560>>>(qh, kh, vh, msk, attn);

    // 4) projection
    proj_kernel<<<dim3(16, 128), 256>>>(attn, Wo, bo, out);
}